// round 11
// baseline (speedup 1.0000x reference)
#include <cuda_runtime.h>
#include <cstdint>

#define NCTA 128
#define NTHR 256

// -------- device scratch (no allocation allowed) --------
__device__ float g_G0[(size_t)1024 * 64 * 2048];   // [t][b][n] input proj + biases
__device__ float g_ga[64 * 2048];                  // stack0 gates
__device__ float g_gb[64 * 2048];                  // stack1 gates
__device__ float g_H0[64 * 512], g_C0[64 * 512];
__device__ float g_H1[64 * 512], g_C1[64 * 512];
__device__ float g_X1[64 * 512];                   // residual input to stack1
__device__ unsigned g_bar;

typedef unsigned long long ull;
#define FMA2(d, a, b) asm("fma.rn.f32x2 %0, %1, %2, %0;" : "+l"(d) : "l"(a), "l"(b))

__device__ __forceinline__ float lohi(ull v) {
    return __uint_as_float((unsigned)v) + __uint_as_float((unsigned)(v >> 32));
}
__device__ __forceinline__ float sigf(float x) { return 1.f / (1.f + __expf(-x)); }

__device__ __forceinline__ void gbar(unsigned& ph) {
    __syncthreads();
    ph += NCTA;
    if (threadIdx.x == 0) {
        __threadfence();
        atomicAdd(&g_bar, 1u);
        while (*(volatile unsigned*)&g_bar < ph) __nanosleep(64);
        __threadfence();
    }
    __syncthreads();
}

// -------- init: zero states, reset barrier --------
__global__ void init_kernel() {
    int i = blockIdx.x * blockDim.x + threadIdx.x;
    if (i == 0) g_bar = 0;
    if (i < 64 * 512) { g_H0[i] = 0.f; g_C0[i] = 0.f; g_H1[i] = 0.f; g_C1[i] = 0.f; }
}

// -------- G0 = seq @ W_ih0^T + b_ih0 + b_hh0  (parallel over t) --------
__global__ __launch_bounds__(NTHR) void g0_kernel(
    const float* __restrict__ seq, const float* __restrict__ Wih,
    const float* __restrict__ bih, const float* __restrict__ bhh)
{
    __shared__ float xs[64 * 68], ws[64 * 68];
    const int t = blockIdx.y, nb = blockIdx.x;   // nb: 0..31 (64 n each)
    const int tid = threadIdx.x;
    const int tr = tid >> 4, tc = tid & 15;      // 4 b rows / 4 n cols per thread
    float acc[4][4] = {};
    for (int kc = 0; kc < 8; kc++) {
        __syncthreads();
#pragma unroll
        for (int i = 0; i < 4; i++) {
            int s = tid + i * 256, r = s >> 4, k4 = s & 15;
            *(float4*)&xs[r * 68 + k4 * 4] =
                *(const float4*)&seq[((size_t)r * 1024 + t) * 512 + kc * 64 + k4 * 4];
            *(float4*)&ws[r * 68 + k4 * 4] =
                __ldg((const float4*)&Wih[((size_t)(nb * 64 + r)) * 512 + kc * 64 + k4 * 4]);
        }
        __syncthreads();
#pragma unroll 4
        for (int kk = 0; kk < 64; kk++) {
            float xr[4], wr[4];
#pragma unroll
            for (int i = 0; i < 4; i++) xr[i] = xs[(tr * 4 + i) * 68 + kk];
#pragma unroll
            for (int j = 0; j < 4; j++) wr[j] = ws[(tc * 4 + j) * 68 + kk];
#pragma unroll
            for (int i = 0; i < 4; i++)
#pragma unroll
                for (int j = 0; j < 4; j++) acc[i][j] += xr[i] * wr[j];
        }
    }
#pragma unroll
    for (int i = 0; i < 4; i++)
#pragma unroll
        for (int j = 0; j < 4; j++) {
            int n = nb * 64 + tc * 4 + j, bb = tr * 4 + i;
            g_G0[((size_t)t * 64 + bb) * 2048 + n] = acc[i][j] + __ldg(&bih[n]) + __ldg(&bhh[n]);
        }
}

// -------- persistent recurrence kernel --------
__global__ __launch_bounds__(NTHR, 1) void lstm_kernel(
    const float* __restrict__ seq, const int* __restrict__ slen,
    const float* __restrict__ Wih, const float* __restrict__ Whh,
    const float* __restrict__ bih, const float* __restrict__ bhh,
    float* __restrict__ out)
{
    extern __shared__ float sm[];
    float* ws0 = sm;                   // [16][516]  W_hh0 rows
    float* ws1 = sm + 16 * 516;        // [16][1028] [W_ih1 | W_hh1] rows
    float* xs  = ws1 + 16 * 1028;      // [64][132]  activation chunk

    const int tid = threadIdx.x;
    const int b  = tid >> 2, ng = tid & 3;          // gemm mapping
    const int nbase = blockIdx.x * 16;
    const int gcell = blockIdx.x * NTHR + tid;      // pointwise cell = cb*512+cj
    const int cb = gcell >> 9, cj = gcell & 511;
    const int mylen = __ldg(&slen[cb]);

    // biases for stack1 gates of this cell (constant over t)
    const float b1i = __ldg(&bih[2048 + cj])        + __ldg(&bhh[2048 + cj]);
    const float b1f = __ldg(&bih[2048 + 512 + cj])  + __ldg(&bhh[2048 + 512 + cj]);
    const float b1g = __ldg(&bih[2048 + 1024 + cj]) + __ldg(&bhh[2048 + 1024 + cj]);
    const float b1o = __ldg(&bih[2048 + 1536 + cj]) + __ldg(&bhh[2048 + 1536 + cj]);

    // ---- load resident weights into SMEM ----
#pragma unroll
    for (int i = 0; i < 8; i++) {
        int s = tid + i * 256, r = s >> 7, k4 = s & 127;
        *(float4*)&ws0[r * 516 + k4 * 4] =
            __ldg((const float4*)&Whh[((size_t)(nbase + r)) * 512 + k4 * 4]);
    }
#pragma unroll
    for (int i = 0; i < 16; i++) {
        int s = tid + i * 256, r = s >> 8, k4 = s & 255;
        const float* src = (k4 < 128)
            ? &Wih[((size_t)(2048 + nbase + r)) * 512 + k4 * 4]
            : &Whh[((size_t)(2048 + nbase + r)) * 512 + (k4 - 128) * 4];
        *(float4*)&ws1[r * 1028 + k4 * 4] = __ldg((const float4*)src);
    }
    __syncthreads();

    unsigned ph = 0;
    for (int t = 0; t < 1024; t++) {
        // ===== window 1: pointwise-1(t-1)  +  gemm-0(t) =====
        if (t > 0) {
            int tp = t - 1;
            float gi = __ldcg(&g_gb[cb * 2048 + cj]) + b1i;
            float gf = __ldcg(&g_gb[cb * 2048 + 512 + cj]) + b1f;
            float gg = __ldcg(&g_gb[cb * 2048 + 1024 + cj]) + b1g;
            float go = __ldcg(&g_gb[cb * 2048 + 1536 + cj]) + b1o;
            float cs = sigf(gf) * __ldcg(&g_C1[gcell]) + sigf(gi) * tanhf(gg);
            float hs = sigf(go) * tanhf(cs);
            float hx = hs + __ldcg(&g_X1[gcell]);
            bool act = tp < mylen;
            out[((size_t)cb * 1024 + tp) * 512 + cj] = act ? hx : 0.f;
            if (act) { __stcg(&g_H1[gcell], hs); __stcg(&g_C1[gcell], cs); }
        }
        {   // gemm-0: g_ga = G0[t] + H0 @ W_hh0^T
            ull acc[4];
#pragma unroll
            for (int j = 0; j < 4; j++)
                acc[j] = (ull)__float_as_uint(
                    __ldg(&g_G0[((size_t)t * 64 + b) * 2048 + nbase + j * 4 + ng]));
            for (int kc = 0; kc < 4; kc++) {
                __syncthreads();
#pragma unroll
                for (int i = 0; i < 8; i++) {
                    int s = tid + i * 256, bb = s >> 5, c4 = s & 31;
                    *(float4*)&xs[bb * 132 + c4 * 4] =
                        __ldcg((const float4*)&g_H0[bb * 512 + kc * 128 + c4 * 4]);
                }
                __syncthreads();
                const ulonglong2* xp = (const ulonglong2*)&xs[b * 132];
#pragma unroll 8
                for (int k4 = 0; k4 < 32; k4++) {
                    ulonglong2 xv = xp[k4];
#pragma unroll
                    for (int j = 0; j < 4; j++) {
                        ulonglong2 wv = *(const ulonglong2*)
                            &ws0[(j * 4 + ng) * 516 + kc * 128 + k4 * 4];
                        FMA2(acc[j], xv.x, wv.x);
                        FMA2(acc[j], xv.y, wv.y);
                    }
                }
            }
#pragma unroll
            for (int j = 0; j < 4; j++)
                __stcg(&g_ga[b * 2048 + nbase + j * 4 + ng], lohi(acc[j]));
        }
        gbar(ph);

        // ===== window 2: pointwise-0(t) =====
        {
            float gi = __ldcg(&g_ga[cb * 2048 + cj]);
            float gf = __ldcg(&g_ga[cb * 2048 + 512 + cj]);
            float gg = __ldcg(&g_ga[cb * 2048 + 1024 + cj]);
            float go = __ldcg(&g_ga[cb * 2048 + 1536 + cj]);
            float cs = sigf(gf) * __ldcg(&g_C0[gcell]) + sigf(gi) * tanhf(gg);
            float hs = sigf(go) * tanhf(cs);
            if (t < mylen) { __stcg(&g_H0[gcell], hs); __stcg(&g_C0[gcell], cs); }
            float xv = __ldg(&seq[((size_t)cb * 1024 + t) * 512 + cj]);
            __stcg(&g_X1[gcell], hs + xv);
        }
        gbar(ph);

        // ===== window 3: gemm-1(t): g_gb = X1 @ W_ih1^T + H1 @ W_hh1^T =====
        {
            ull acc[4] = {0, 0, 0, 0};
            for (int kc = 0; kc < 8; kc++) {
                const float* src = (kc < 4) ? (g_X1 + kc * 128) : (g_H1 + (kc - 4) * 128);
                __syncthreads();
#pragma unroll
                for (int i = 0; i < 8; i++) {
                    int s = tid + i * 256, bb = s >> 5, c4 = s & 31;
                    *(float4*)&xs[bb * 132 + c4 * 4] =
                        __ldcg((const float4*)&src[bb * 512 + c4 * 4]);
                }
                __syncthreads();
                const ulonglong2* xp = (const ulonglong2*)&xs[b * 132];
#pragma unroll 8
                for (int k4 = 0; k4 < 32; k4++) {
                    ulonglong2 xv = xp[k4];
#pragma unroll
                    for (int j = 0; j < 4; j++) {
                        ulonglong2 wv = *(const ulonglong2*)
                            &ws1[(j * 4 + ng) * 1028 + kc * 128 + k4 * 4];
                        FMA2(acc[j], xv.x, wv.x);
                        FMA2(acc[j], xv.y, wv.y);
                    }
                }
            }
#pragma unroll
            for (int j = 0; j < 4; j++)
                __stcg(&g_gb[b * 2048 + nbase + j * 4 + ng], lohi(acc[j]));
        }
        gbar(ph);
    }

    // ===== final pointwise-1(1023) =====
    {
        int tp = 1023;
        float gi = __ldcg(&g_gb[cb * 2048 + cj]) + b1i;
        float gf = __ldcg(&g_gb[cb * 2048 + 512 + cj]) + b1f;
        float gg = __ldcg(&g_gb[cb * 2048 + 1024 + cj]) + b1g;
        float go = __ldcg(&g_gb[cb * 2048 + 1536 + cj]) + b1o;
        float cs = sigf(gf) * __ldcg(&g_C1[gcell]) + sigf(gi) * tanhf(gg);
        float hs = sigf(go) * tanhf(cs);
        float hx = hs + __ldcg(&g_X1[gcell]);
        bool act = tp < mylen;
        out[((size_t)cb * 1024 + tp) * 512 + cj] = act ? hx : 0.f;
        if (act) { __stcg(&g_H1[gcell], hs); __stcg(&g_C1[gcell], cs); }
    }
    gbar(ph);

    // ===== tail: final h, c =====
    {
        const size_t HO = (size_t)64 * 1024 * 512;
        out[HO + gcell]               = __ldcg(&g_H0[gcell]);
        out[HO + 32768 + gcell]       = __ldcg(&g_H1[gcell]);
        out[HO + 65536 + gcell]       = __ldcg(&g_C0[gcell]);
        out[HO + 65536 + 32768 + gcell] = __ldcg(&g_C1[gcell]);
    }
}

extern "C" void kernel_launch(void* const* d_in, const int* in_sizes, int n_in,
                              void* d_out, int out_size) {
    const float* seq  = (const float*)d_in[0];
    const int*   slen = (const int*)d_in[1];
    const float* Wih  = (const float*)d_in[2];
    const float* Whh  = (const float*)d_in[3];
    const float* bih  = (const float*)d_in[4];
    const float* bhh  = (const float*)d_in[5];
    float* out = (float*)d_out;

    init_kernel<<<128, 256>>>();
    g0_kernel<<<dim3(32, 1024), NTHR>>>(seq, Wih, bih, bhh);

    const int smem = (16 * 516 + 16 * 1028 + 64 * 132) * 4;   // 132608 B
    static int attr_set = 0;
    cudaFuncSetAttribute(lstm_kernel, cudaFuncAttributeMaxDynamicSharedMemorySize, smem);
    (void)attr_set;
    lstm_kernel<<<NCTA, NTHR, smem>>>(seq, slen, Wih, Whh, bih, bhh, out);
}

// round 12
// speedup vs baseline: 1.4960x; 1.4960x over previous
#include <cuda_runtime.h>
#include <cstdint>

#define NCTA 128
#define NTHR 256
typedef unsigned long long ull;

// -------- device scratch --------
__device__ float g_G0[(size_t)1024 * 64 * 2048];   // [t][b][n] input proj + stack0 biases
__device__ float g_H0[2][64 * 512];
__device__ float g_H1[2][64 * 512];
__device__ float g_X1[2][64 * 512];
__device__ unsigned g_bar;

#define FMA2(d, a, b) asm("fma.rn.f32x2 %0, %1, %2, %0;" : "+l"(d) : "l"(a), "l"(b))
#define CPWAIT   asm volatile("cp.async.wait_group 0;" ::: "memory")
#define CPCOMMIT asm volatile("cp.async.commit_group;" ::: "memory")

__device__ __forceinline__ void cpa16(float* d, const float* s) {
    unsigned u = (unsigned)__cvta_generic_to_shared(d);
    asm volatile("cp.async.cg.shared.global [%0], [%1], 16;" :: "r"(u), "l"(s));
}
__device__ __forceinline__ float lohi(ull v) {
    return __uint_as_float((unsigned)v) + __uint_as_float((unsigned)(v >> 32));
}
__device__ __forceinline__ float sigf(float x) { return 1.f / (1.f + __expf(-x)); }

__device__ __forceinline__ void gbar(unsigned& ph) {
    __syncthreads();
    ph += NCTA;
    if (threadIdx.x == 0) {
        __threadfence();
        atomicAdd(&g_bar, 1u);
        while (*(volatile unsigned*)&g_bar < ph) __nanosleep(64);
        __threadfence();
    }
    __syncthreads();
}

__global__ void init_kernel() {
    int i = blockIdx.x * blockDim.x + threadIdx.x;
    if (i == 0) g_bar = 0;
    if (i < 64 * 512) { g_H1[0][i] = 0.f; g_H1[1][i] = 0.f; }
}

// -------- G0 = seq @ W_ih0^T + b_ih0 + b_hh0, f32x2, conflict-free W tile --------
__global__ __launch_bounds__(NTHR) void g0_kernel(
    const float* __restrict__ seq, const float* __restrict__ Wih,
    const float* __restrict__ bih, const float* __restrict__ bhh)
{
    __shared__ float  xs[64 * 68];
    __shared__ float2 wst[32 * 66];
    const int t = blockIdx.y, nb = blockIdx.x;
    const int tid = threadIdx.x, tr = tid >> 4, tc = tid & 15;
    ull acc[4][4] = {};
    for (int kc = 0; kc < 8; kc++) {
        __syncthreads();
#pragma unroll
        for (int i = 0; i < 4; i++) {
            int s = i * 256 + tid, rr = s >> 4, c4 = s & 15;
            *(float4*)&xs[rr * 68 + c4 * 4] =
                *(const float4*)&seq[((size_t)rr * 1024 + t) * 512 + kc * 64 + c4 * 4];
            float4 wv = __ldg((const float4*)&Wih[((size_t)(nb * 64 + rr)) * 512 + kc * 64 + c4 * 4]);
            wst[(c4 * 2) * 66 + rr]     = make_float2(wv.x, wv.y);
            wst[(c4 * 2 + 1) * 66 + rr] = make_float2(wv.z, wv.w);
        }
        __syncthreads();
        const ull* wstu = (const ull*)wst;
#pragma unroll 4
        for (int k2 = 0; k2 < 32; k2++) {
            ull xr[4], wr[4];
#pragma unroll
            for (int i = 0; i < 4; i++) xr[i] = *(const ull*)&xs[(tr * 4 + i) * 68 + k2 * 2];
#pragma unroll
            for (int j = 0; j < 4; j++) wr[j] = wstu[k2 * 66 + j * 16 + tc];
#pragma unroll
            for (int i = 0; i < 4; i++)
#pragma unroll
                for (int j = 0; j < 4; j++) FMA2(acc[i][j], xr[i], wr[j]);
        }
    }
#pragma unroll
    for (int i = 0; i < 4; i++)
#pragma unroll
        for (int j = 0; j < 4; j++) {
            int n = nb * 64 + j * 16 + tc, b = tr * 4 + i;
            g_G0[((size_t)t * 64 + b) * 2048 + n] =
                lohi(acc[i][j]) + __ldg(&bih[n]) + __ldg(&bhh[n]);
        }
}

// -------- persistent recurrence: weights in registers, 1 bar/step --------
__global__ __launch_bounds__(NTHR, 1) void lstm_kernel(
    const float* __restrict__ seq, const int* __restrict__ slen,
    const float* __restrict__ Wih, const float* __restrict__ Whh,
    const float* __restrict__ bih, const float* __restrict__ bhh,
    float* __restrict__ out)
{
    extern __shared__ float sb[];            // 2 x 17408 stage halves + red
    float* red = sb + 2 * 17408;             // [64 b][16 r]

    const int tid = threadIdx.x;
    const int w = tid >> 5, l = tid & 31, ks = l >> 1, rl = l & 1;
    const int r = w * 2 + rl, g = r >> 2, jl = r & 3;
    const int j = blockIdx.x * 4 + jl;
    const int n0 = g * 512 + j, n1 = 2048 + n0;
    const int pb = tid >> 2, pjl = tid & 3;
    const int pj = blockIdx.x * 4 + pjl, gcell = pb * 512 + pj;
    const int mylen = __ldg(&slen[pb]);
    const float b1i = __ldg(&bih[2048 + pj])        + __ldg(&bhh[2048 + pj]);
    const float b1f = __ldg(&bih[2048 + 512 + pj])  + __ldg(&bhh[2048 + 512 + pj]);
    const float b1g = __ldg(&bih[2048 + 1024 + pj]) + __ldg(&bhh[2048 + 1024 + pj]);
    const float b1o = __ldg(&bih[2048 + 1536 + pj]) + __ldg(&bhh[2048 + 1536 + pj]);

    // ---- weights into registers ----
    ull w0[16], w1[32];
    {
        const float* p0 = Whh + (size_t)n0 * 512 + ks * 32;
#pragma unroll
        for (int i = 0; i < 16; i++) w0[i] = *(const ull*)(p0 + 2 * i);
        const float* p1 = (ks < 8) ? (Wih + (size_t)n1 * 512 + ks * 64)
                                   : (Whh + (size_t)n1 * 512 + (ks - 8) * 64);
#pragma unroll
        for (int i = 0; i < 32; i++) w1[i] = *(const ull*)(p1 + 2 * i);
    }
    float c0 = 0.f, c1 = 0.f, h0reg = 0.f, h1reg = 0.f, x1reg = 0.f;
    unsigned ph = 0;

#define STAGE1(cc) do { \
    const float* _x = g_X1[p]; const float* _h = g_H1[p ^ 1]; int _hf = (cc) & 1; \
    _Pragma("unroll") for (int q = 0; q < 16; q++) { \
        int fl = q * 256 + tid, bl = fl >> 8, k4 = fl & 255, gb = (cc) * 16 + bl; \
        const float* s_ = (k4 < 128) ? (_x + gb * 512 + k4 * 4) : (_h + gb * 512 + (k4 - 128) * 4); \
        cpa16(&sb[_hf * 17408 + bl * 1088 + (k4 >> 4) * 68 + (k4 & 15) * 4], s_); } \
    } while (0)

#define STAGE0(cc) do { \
    const float* _h = g_H0[p]; int _hf = (cc) & 1; \
    _Pragma("unroll") for (int q = 0; q < 8; q++) { \
        int fl = q * 256 + tid, bl = fl >> 7, k4 = fl & 127, gb = (cc) * 16 + bl; \
        cpa16(&sb[_hf * 17408 + bl * 576 + (k4 >> 3) * 36 + (k4 & 7) * 4], \
              _h + gb * 512 + k4 * 4); } \
    } while (0)

#define REDUCE_STORE(cc, bl) do { \
    float s_ = lohi(acc); \
    s_ += __shfl_xor_sync(~0u, s_, 2);  s_ += __shfl_xor_sync(~0u, s_, 4); \
    s_ += __shfl_xor_sync(~0u, s_, 8);  s_ += __shfl_xor_sync(~0u, s_, 16); \
    if (l < 2) red[((cc) * 16 + (bl)) * 16 + r] = s_; } while (0)

#define COMP1(cc) do { int _hf = (cc) & 1; \
    _Pragma("unroll 2") for (int bl = 0; bl < 16; bl++) { \
        const float* bp = &sb[_hf * 17408 + bl * 1088 + ks * 68]; \
        ull acc = 0; \
        _Pragma("unroll") for (int i = 0; i < 16; i++) { \
            ulonglong2 xv = *(const ulonglong2*)(bp + i * 4); \
            FMA2(acc, xv.x, w1[2 * i]); FMA2(acc, xv.y, w1[2 * i + 1]); } \
        REDUCE_STORE(cc, bl); } } while (0)

#define COMP0(cc) do { int _hf = (cc) & 1; \
    _Pragma("unroll 2") for (int bl = 0; bl < 16; bl++) { \
        const float* bp = &sb[_hf * 17408 + bl * 576 + ks * 36]; \
        ull acc = 0; \
        _Pragma("unroll") for (int i = 0; i < 8; i++) { \
            ulonglong2 xv = *(const ulonglong2*)(bp + i * 4); \
            FMA2(acc, xv.x, w0[2 * i]); FMA2(acc, xv.y, w0[2 * i + 1]); } \
        REDUCE_STORE(cc, bl); } } while (0)

#define PW0(t1, pw, addred) do { \
    size_t gb0 = ((size_t)(t1) * 64 + pb) * 2048 + pj; \
    float gi = __ldg(&g_G0[gb0])        + ((addred) ? red[pb * 16 + pjl]      : 0.f); \
    float gf = __ldg(&g_G0[gb0 + 512])  + ((addred) ? red[pb * 16 + 4 + pjl]  : 0.f); \
    float gg = __ldg(&g_G0[gb0 + 1024]) + ((addred) ? red[pb * 16 + 8 + pjl]  : 0.f); \
    float go = __ldg(&g_G0[gb0 + 1536]) + ((addred) ? red[pb * 16 + 12 + pjl] : 0.f); \
    float cs = sigf(gf) * c0 + sigf(gi) * tanhf(gg); \
    float hs = sigf(go) * tanhf(cs); \
    if ((t1) < mylen) { c0 = cs; h0reg = hs; } \
    __stcg(&g_H0[pw][gcell], h0reg); \
    float xv = __ldg(&seq[((size_t)pb * 1024 + (t1)) * 512 + pj]); \
    x1reg = hs + xv; \
    __stcg(&g_X1[pw][gcell], x1reg); } while (0)

    // ---- prologue: pw0(0) (gemm term is zero since h0(-1)=0) ----
    PW0(0, 0, 0);
    gbar(ph);

    for (int t = 0; t < 1024; t++) {
        const int p = t & 1;
        // ===== gemm1(t) =====
        STAGE1(0); CPCOMMIT;
#pragma unroll 1
        for (int cc = 0; cc < 4; cc++) {
            CPWAIT; __syncthreads();
            if (cc < 3)          { STAGE1(cc + 1); CPCOMMIT; }
            else if (t < 1023)   { STAGE0(0);      CPCOMMIT; }
            COMP1(cc);
        }
        __syncthreads();
        // ===== pw1(t) =====
        {
            float gi = red[pb * 16 + pjl]      + b1i;
            float gf = red[pb * 16 + 4 + pjl]  + b1f;
            float gg = red[pb * 16 + 8 + pjl]  + b1g;
            float go = red[pb * 16 + 12 + pjl] + b1o;
            float cs = sigf(gf) * c1 + sigf(gi) * tanhf(gg);
            float hs = sigf(go) * tanhf(cs);
            bool act = t < mylen;
            out[((size_t)pb * 1024 + t) * 512 + pj] = act ? (hs + x1reg) : 0.f;
            if (act) { c1 = cs; h1reg = hs; }
            __stcg(&g_H1[p][gcell], h1reg);
        }
        if (t == 1023) break;
        // ===== gemm0(t+1) =====
#pragma unroll 1
        for (int cc = 0; cc < 4; cc++) {
            CPWAIT; __syncthreads();
            if (cc < 3) { STAGE0(cc + 1); CPCOMMIT; }
            COMP0(cc);
        }
        __syncthreads();
        // ===== pw0(t+1) =====
        PW0(t + 1, p ^ 1, 1);
        gbar(ph);
    }

    // ---- tail: final h, c ----
    const size_t HO = (size_t)64 * 1024 * 512;
    out[HO + gcell]                 = h0reg;
    out[HO + 32768 + gcell]         = h1reg;
    out[HO + 65536 + gcell]         = c0;
    out[HO + 65536 + 32768 + gcell] = c1;
}

extern "C" void kernel_launch(void* const* d_in, const int* in_sizes, int n_in,
                              void* d_out, int out_size) {
    const float* seq  = (const float*)d_in[0];
    const int*   slen = (const int*)d_in[1];
    const float* Wih  = (const float*)d_in[2];
    const float* Whh  = (const float*)d_in[3];
    const float* bih  = (const float*)d_in[4];
    const float* bhh  = (const float*)d_in[5];
    float* out = (float*)d_out;

    init_kernel<<<128, 256>>>();
    g0_kernel<<<dim3(32, 1024), NTHR>>>(seq, Wih, bih, bhh);

    const int smem = (2 * 17408 + 1024) * 4;   // 143360 B
    cudaFuncSetAttribute(lstm_kernel, cudaFuncAttributeMaxDynamicSharedMemorySize, smem);
    lstm_kernel<<<NCTA, NTHR, smem>>>(seq, slen, Wih, Whh, bih, bhh, out);
}

// round 13
// speedup vs baseline: 2.0728x; 1.3855x over previous
#include <cuda_runtime.h>
#include <cstdint>

#define NCTA 128
#define NTHR 256
typedef unsigned long long ull;

// -------- device scratch --------
__device__ __align__(128) float g_G0[(size_t)1024 * 2048 * 64];  // [t][n][b]
__device__ __align__(128) float g_X1P[2][512 * 64];   // [(k>>1)*128 + b*2 + (k&1)]
__device__ __align__(128) float g_H1P[2][512 * 64];
__device__ __align__(128) float g_H0P[2][512 * 64];
__device__ unsigned g_bar;

#define FMA2(d, a, b) asm("fma.rn.f32x2 %0, %1, %2, %0;" : "+l"(d) : "l"(a), "l"(b))
#define CPWAIT   asm volatile("cp.async.wait_group 0;" ::: "memory")
#define CPCOMMIT asm volatile("cp.async.commit_group;" ::: "memory")

__device__ __forceinline__ void cpa16(float* d, const float* s) {
    unsigned u = (unsigned)__cvta_generic_to_shared(d);
    asm volatile("cp.async.cg.shared.global [%0], [%1], 16;" :: "r"(u), "l"(s));
}
__device__ __forceinline__ float lohi(ull v) {
    return __uint_as_float((unsigned)v) + __uint_as_float((unsigned)(v >> 32));
}
__device__ __forceinline__ float sigf(float x) { return 1.f / (1.f + __expf(-x)); }

__device__ __forceinline__ void gbar(unsigned& ph) {
    __syncthreads();
    ph += NCTA;
    if (threadIdx.x == 0) {
        __threadfence();
        atomicAdd(&g_bar, 1u);
        while (*(volatile unsigned*)&g_bar < ph) __nanosleep(64);
        __threadfence();
    }
    __syncthreads();
}

__global__ void init_kernel() {
    int i = blockIdx.x * blockDim.x + threadIdx.x;
    if (i == 0) g_bar = 0;
    if (i < 512 * 64) { g_H1P[0][i] = 0.f; g_H1P[1][i] = 0.f; }
}

// -------- G0[t][n][b] = (seq @ W_ih0^T)(b,n) + b_ih0[n] + b_hh0[n] --------
__global__ __launch_bounds__(NTHR) void g0_kernel(
    const float* __restrict__ seq, const float* __restrict__ Wih,
    const float* __restrict__ bih, const float* __restrict__ bhh)
{
    __shared__ float  xs[64 * 68];
    __shared__ float2 wst[32 * 68];
    const int t = blockIdx.y, nb = blockIdx.x;
    const int tid = threadIdx.x, tr = tid >> 4, tc = tid & 15;
    ull acc[4][4] = {};
    for (int kc = 0; kc < 8; kc++) {
        __syncthreads();
#pragma unroll
        for (int i = 0; i < 4; i++) {
            int s = i * 256 + tid, rr = s >> 4, c4 = s & 15;
            *(float4*)&xs[rr * 68 + c4 * 4] =
                *(const float4*)&seq[((size_t)rr * 1024 + t) * 512 + kc * 64 + c4 * 4];
            float4 wv = __ldg((const float4*)&Wih[((size_t)(nb * 64 + rr)) * 512 + kc * 64 + c4 * 4]);
            wst[(c4 * 2) * 66 + rr]     = make_float2(wv.x, wv.y);
            wst[(c4 * 2 + 1) * 66 + rr] = make_float2(wv.z, wv.w);
        }
        __syncthreads();
        const ull* wstu = (const ull*)wst;
#pragma unroll 4
        for (int k2 = 0; k2 < 32; k2++) {
            ull xr[4], wr[4];
#pragma unroll
            for (int i = 0; i < 4; i++) xr[i] = *(const ull*)&xs[(tr * 4 + i) * 68 + k2 * 2];
#pragma unroll
            for (int j = 0; j < 4; j++) wr[j] = wstu[k2 * 66 + j * 16 + tc];
#pragma unroll
            for (int i = 0; i < 4; i++)
#pragma unroll
                for (int j = 0; j < 4; j++) FMA2(acc[i][j], xr[i], wr[j]);
        }
    }
    // transpose through SMEM, add biases, store [n][b] coalesced
    float* smt = (float*)wst;            // 4352 floats, stride 68 over 64 rows
    __syncthreads();
#pragma unroll
    for (int i = 0; i < 4; i++)
#pragma unroll
        for (int j = 0; j < 4; j++)
            smt[(j * 16 + tc) * 68 + tr * 4 + i] = lohi(acc[i][j]);
    __syncthreads();
    for (int u = tid; u < 1024; u += NTHR) {
        int nloc = u >> 4, bq = u & 15;
        int n = nb * 64 + nloc;
        float bias = __ldg(&bih[n]) + __ldg(&bhh[n]);
        float4 v = *(const float4*)&smt[nloc * 68 + bq * 4];
        v.x += bias; v.y += bias; v.z += bias; v.w += bias;
        *(float4*)&g_G0[((size_t)t * 2048 + n) * 64 + bq * 4] = v;
    }
}

// -------- persistent recurrence --------
__global__ __launch_bounds__(NTHR, 1) void lstm_kernel(
    const float* __restrict__ seq, const int* __restrict__ slen,
    const float* __restrict__ Wih, const float* __restrict__ Whh,
    const float* __restrict__ bih, const float* __restrict__ bhh,
    float* __restrict__ out)
{
    extern __shared__ float sb[];
    float* ws1 = sb;                 // [16][1024]
    float* ws0 = sb + 16384;         // [16][512]
    float* xs  = sb + 24576;         // 2 x 8192 stage buffers
    float* red = sb + 40960;         // [4 ks][16 r][64 b]

    const int tid = threadIdx.x, bx = blockIdx.x;
    // gemm mapping: thread = (k-slice, b)
    const int gb = tid & 63, ks = tid >> 6, b2 = gb * 2;
    // pointwise mapping: thread = (pjl, pb), owns cell (pb, pj)
    const int pjl = tid >> 6, pb = tid & 63;
    const int pj = bx * 4 + pjl;
    const int gcell = pb * 512 + pj;
    const int pword = (pj >> 1) * 128 + pb * 2 + (pj & 1);
    const int rb = pjl * 64 + pb;            // red gather base
    const int mylen = __ldg(&slen[pb]);
    const float b1i = __ldg(&bih[2048 + pj])        + __ldg(&bhh[2048 + pj]);
    const float b1f = __ldg(&bih[2048 + 512 + pj])  + __ldg(&bhh[2048 + 512 + pj]);
    const float b1g = __ldg(&bih[2048 + 1024 + pj]) + __ldg(&bhh[2048 + 1024 + pj]);
    const float b1o = __ldg(&bih[2048 + 1536 + pj]) + __ldg(&bhh[2048 + 1536 + pj]);

    // ---- resident weights -> SMEM (rows r = g*4 + jl) ----
    for (int u = tid; u < 4096; u += NTHR) {          // ws1: [Wih1 | Whh1]
        int r = u >> 8, k4 = u & 255;
        int n1 = 2048 + (r >> 2) * 512 + bx * 4 + (r & 3);
        const float* src = (k4 < 128) ? &Wih[(size_t)n1 * 512 + k4 * 4]
                                      : &Whh[(size_t)n1 * 512 + (k4 - 128) * 4];
        *(float4*)&ws1[r * 1024 + k4 * 4] = __ldg((const float4*)src);
    }
    for (int u = tid; u < 2048; u += NTHR) {          // ws0: Whh0
        int r = u >> 7, k4 = u & 127;
        int n0 = (r >> 2) * 512 + bx * 4 + (r & 3);
        *(float4*)&ws0[r * 512 + k4 * 4] =
            __ldg((const float4*)&Whh[(size_t)n0 * 512 + k4 * 4]);
    }
    __syncthreads();

    float c0 = 0.f, c1 = 0.f, h0reg = 0.f, h1reg = 0.f, x1reg = 0.f;
    unsigned ph = 0;

#define STAGE1(c, hf, p) do { \
    const float* _s = ((c) < 4) ? (g_X1P[p] + (c) * 8192) \
                                : (g_H1P[(p) ^ 1] + ((c) - 4) * 8192); \
    float* _d = xs + (hf) * 8192; \
    _Pragma("unroll") for (int q = 0; q < 8; q++) \
        cpa16(_d + (q * NTHR + tid) * 4, _s + (q * NTHR + tid) * 4); \
} while (0)

#define STAGE0(c, hf, p) do { \
    const float* _s = g_H0P[p] + (c) * 8192; \
    float* _d = xs + (hf) * 8192; \
    _Pragma("unroll") for (int q = 0; q < 8; q++) \
        cpa16(_d + (q * NTHR + tid) * 4, _s + (q * NTHR + tid) * 4); \
} while (0)

#define COMP(c, hf, WS, WSTRIDE) do { \
    const float* _x = xs + (hf) * 8192; \
    _Pragma("unroll") for (int blk = 0; blk < 8; blk++) { \
        ull xa = *(const ull*)&_x[(ks * 16 + 2 * blk) * 128 + b2]; \
        ull xb = *(const ull*)&_x[(ks * 16 + 2 * blk + 1) * 128 + b2]; \
        int _k4 = (c) * 32 + ks * 8 + blk; \
        _Pragma("unroll") for (int r = 0; r < 16; r++) { \
            ulonglong2 wv = *(const ulonglong2*)&(WS)[r * (WSTRIDE) + _k4 * 4]; \
            FMA2(acc[r], xa, wv.x); FMA2(acc[r], xb, wv.y); \
        } \
    } \
} while (0)

#define RED_STORE() do { \
    __syncthreads(); \
    _Pragma("unroll") for (int r = 0; r < 16; r++) \
        red[ks * 1024 + r * 64 + gb] = lohi(acc[r]); \
    __syncthreads(); \
} while (0)

#define GATHER(q0, q1, q2, q3) \
    float q0 = red[rb]        + red[1024 + rb]        + red[2048 + rb]        + red[3072 + rb]; \
    float q1 = red[256 + rb]  + red[1024 + 256 + rb]  + red[2048 + 256 + rb]  + red[3072 + 256 + rb]; \
    float q2 = red[512 + rb]  + red[1024 + 512 + rb]  + red[2048 + 512 + rb]  + red[3072 + 512 + rb]; \
    float q3 = red[768 + rb]  + red[1024 + 768 + rb]  + red[2048 + 768 + rb]  + red[3072 + 768 + rb];

#define PW0(t1, pw, ADDRED) do { \
    size_t _g = ((size_t)(t1) * 2048 + pj) * 64 + pb; \
    float q0 = __ldg(&g_G0[_g]); \
    float q1 = __ldg(&g_G0[_g + 512 * 64]); \
    float q2 = __ldg(&g_G0[_g + 1024 * 64]); \
    float q3 = __ldg(&g_G0[_g + 1536 * 64]); \
    if (ADDRED) { GATHER(a0, a1, a2, a3); q0 += a0; q1 += a1; q2 += a2; q3 += a3; } \
    float _cs = sigf(q1) * c0 + sigf(q0) * tanhf(q2); \
    float _hs = sigf(q3) * tanhf(_cs); \
    if ((t1) < mylen) { c0 = _cs; h0reg = _hs; } \
    __stcg(&g_H0P[pw][pword], h0reg); \
    float _xv = __ldg(&seq[((size_t)pb * 1024 + (t1)) * 512 + pj]); \
    x1reg = _hs + _xv; \
    __stcg(&g_X1P[pw][pword], x1reg); \
} while (0)

    // ---- prologue: pw0(0); gemm0 term is zero (h0(-1)=0) ----
    PW0(0, 0, 0);
    gbar(ph);

#pragma unroll 1
    for (int t = 0; t < 1024; t++) {
        const int p = t & 1;
        ull acc[16];
        // ===== gemm1(t): [X1(t); H1(t-1)] @ [Wih1; Whh1]^T =====
        STAGE1(0, 0, p); CPCOMMIT;
#pragma unroll
        for (int r = 0; r < 16; r++) acc[r] = 0;
#pragma unroll 1
        for (int cc = 0; cc < 8; cc++) {
            CPWAIT; __syncthreads();
            if (cc < 7)        { STAGE1(cc + 1, (cc + 1) & 1, p); CPCOMMIT; }
            else if (t < 1023) { STAGE0(0, 0, p);                 CPCOMMIT; }
            COMP(cc, cc & 1, ws1, 1024);
        }
        RED_STORE();
        // ===== pw1(t) =====
        {
            GATHER(q0, q1, q2, q3);
            float cs = sigf(q1 + b1f) * c1 + sigf(q0 + b1i) * tanhf(q2 + b1g);
            float hs = sigf(q3 + b1o) * tanhf(cs);
            bool act = t < mylen;
            out[((size_t)pb * 1024 + t) * 512 + pj] = act ? (hs + x1reg) : 0.f;
            if (act) { c1 = cs; h1reg = hs; }
            __stcg(&g_H1P[p][pword], h1reg);
        }
        if (t == 1023) break;
        // ===== gemm0(t+1): H0(t) @ Whh0^T =====
#pragma unroll
        for (int r = 0; r < 16; r++) acc[r] = 0;
#pragma unroll 1
        for (int cc = 0; cc < 4; cc++) {
            CPWAIT; __syncthreads();
            if (cc < 3) { STAGE0(cc + 1, (cc + 1) & 1, p); CPCOMMIT; }
            COMP(cc, cc & 1, ws0, 512);
        }
        RED_STORE();
        // ===== pw0(t+1) =====
        PW0(t + 1, p ^ 1, 1);
        gbar(ph);
    }

    // ---- tail: final h, c ----
    const size_t HO = (size_t)64 * 1024 * 512;
    out[HO + gcell]                 = h0reg;
    out[HO + 32768 + gcell]         = h1reg;
    out[HO + 65536 + gcell]         = c0;
    out[HO + 98304 + gcell]         = c1;
}

extern "C" void kernel_launch(void* const* d_in, const int* in_sizes, int n_in,
                              void* d_out, int out_size) {
    const float* seq  = (const float*)d_in[0];
    const int*   slen = (const int*)d_in[1];
    const float* Wih  = (const float*)d_in[2];
    const float* Whh  = (const float*)d_in[3];
    const float* bih  = (const float*)d_in[4];
    const float* bhh  = (const float*)d_in[5];
    float* out = (float*)d_out;

    init_kernel<<<128, 256>>>();
    g0_kernel<<<dim3(32, 1024), NTHR>>>(seq, Wih, bih, bhh);

    const int smem = (16384 + 8192 + 2 * 8192 + 4096) * 4;   // 180224 B
    cudaFuncSetAttribute(lstm_kernel, cudaFuncAttributeMaxDynamicSharedMemorySize, smem);
    lstm_kernel<<<NCTA, NTHR, smem>>>(seq, slen, Wih, Whh, bih, bhh, out);
}

// round 14
// speedup vs baseline: 2.8916x; 1.3950x over previous
#include <cuda_runtime.h>
#include <cstdint>

#define NCTA 128
#define NTHR 256
typedef unsigned long long ull;

// -------- device scratch --------
__device__ __align__(128) float g_G0[(size_t)1024 * 2048 * 64];  // [t][n][b] fp32 exact
__device__ __align__(128) float g_X1[2][64 * 512];   // [b][kperm] tf32-rounded
__device__ __align__(128) float g_H1[2][64 * 512];
__device__ __align__(128) float g_H0[2][64 * 512];
__device__ __align__(128) float g_WP[(size_t)NCTA * 192 * 128];  // permuted tf32 weights
__device__ unsigned g_bar;

#define FMA2(d, a, b) asm("fma.rn.f32x2 %0, %1, %2, %0;" : "+l"(d) : "l"(a), "l"(b))
#define CPWAIT   asm volatile("cp.async.wait_group 0;" ::: "memory")
#define CPCOMMIT asm volatile("cp.async.commit_group;" ::: "memory")

#define MMA(d, a0, a1, a2, a3, b0, b1) \
    asm("mma.sync.aligned.m16n8k8.row.col.f32.tf32.tf32.f32 " \
        "{%0,%1,%2,%3}, {%4,%5,%6,%7}, {%8,%9}, {%0,%1,%2,%3};" \
        : "+f"(d[0]), "+f"(d[1]), "+f"(d[2]), "+f"(d[3]) \
        : "r"(a0), "r"(a1), "r"(a2), "r"(a3), "r"(b0), "r"(b1))

__device__ __forceinline__ void cpa16(float* d, const float* s) {
    unsigned u = (unsigned)__cvta_generic_to_shared(d);
    asm volatile("cp.async.cg.shared.global [%0], [%1], 16;" :: "r"(u), "l"(s));
}
__device__ __forceinline__ float lohi(ull v) {
    return __uint_as_float((unsigned)v) + __uint_as_float((unsigned)(v >> 32));
}
__device__ __forceinline__ float sigf(float x) { return 1.f / (1.f + __expf(-x)); }
__device__ __forceinline__ float tf32r(float x) {
    unsigned u; asm("cvt.rna.tf32.f32 %0, %1;" : "=r"(u) : "f"(x));
    return __uint_as_float(u);
}

__device__ __forceinline__ void gbar(unsigned& ph) {
    __syncthreads();
    ph += NCTA;
    if (threadIdx.x == 0) {
        __threadfence();
        atomicAdd(&g_bar, 1u);
        while (*(volatile unsigned*)&g_bar < ph) { }
        __threadfence();
    }
    __syncthreads();
}

__global__ void init_kernel() {
    int i = blockIdx.x * blockDim.x + threadIdx.x;
    if (i == 0) g_bar = 0;
    if (i < 64 * 512) { g_H1[0][i] = 0.f; g_H1[1][i] = 0.f; }
}

// -------- permute weights into mma B-fragment order, tf32-rounded --------
__global__ __launch_bounds__(NTHR) void wprep_kernel(
    const float* __restrict__ Wih, const float* __restrict__ Whh)
{
    int bx = blockIdx.x;
    for (int idx = threadIdx.x; idx < 192 * 128; idx += NTHR) {
        int K8 = idx >> 7, li = idx & 127;
        int lane = li >> 2, q = li & 3;
        int nt = q >> 1, breg = q & 1;
        int r = nt * 8 + (lane >> 2);
        int kin = (lane & 3) + breg * 4;
        int nglob = (r >> 2) * 512 + bx * 4 + (r & 3);
        const float* src;
        if (K8 < 64)       src = &Wih[(size_t)(2048 + nglob) * 512 + K8 * 8 + kin];
        else if (K8 < 128) src = &Whh[(size_t)(2048 + nglob) * 512 + (K8 - 64) * 8 + kin];
        else               src = &Whh[(size_t)nglob * 512 + (K8 - 128) * 8 + kin];
        g_WP[(size_t)bx * 24576 + idx] = tf32r(__ldg(src));
    }
}

// -------- G0[t][n][b] = (seq @ W_ih0^T)(b,n) + biases  (exact fp32) --------
__global__ __launch_bounds__(NTHR) void g0_kernel(
    const float* __restrict__ seq, const float* __restrict__ Wih,
    const float* __restrict__ bih, const float* __restrict__ bhh)
{
    __shared__ float  xs[64 * 68];
    __shared__ float2 wst[32 * 66 + 64];
    const int t = blockIdx.y, nb = blockIdx.x;
    const int tid = threadIdx.x, tr = tid >> 4, tc = tid & 15;
    ull acc[4][4] = {};
    for (int kc = 0; kc < 8; kc++) {
        __syncthreads();
#pragma unroll
        for (int i = 0; i < 4; i++) {
            int s = i * 256 + tid, rr = s >> 4, c4 = s & 15;
            *(float4*)&xs[rr * 68 + c4 * 4] =
                *(const float4*)&seq[((size_t)rr * 1024 + t) * 512 + kc * 64 + c4 * 4];
            float4 wv = __ldg((const float4*)&Wih[((size_t)(nb * 64 + rr)) * 512 + kc * 64 + c4 * 4]);
            wst[(c4 * 2) * 66 + rr]     = make_float2(wv.x, wv.y);
            wst[(c4 * 2 + 1) * 66 + rr] = make_float2(wv.z, wv.w);
        }
        __syncthreads();
        const ull* wstu = (const ull*)wst;
#pragma unroll 4
        for (int k2 = 0; k2 < 32; k2++) {
            ull xr[4], wr[4];
#pragma unroll
            for (int i = 0; i < 4; i++) xr[i] = *(const ull*)&xs[(tr * 4 + i) * 68 + k2 * 2];
#pragma unroll
            for (int j = 0; j < 4; j++) wr[j] = wstu[k2 * 66 + j * 16 + tc];
#pragma unroll
            for (int i = 0; i < 4; i++)
#pragma unroll
                for (int j = 0; j < 4; j++) FMA2(acc[i][j], xr[i], wr[j]);
        }
    }
    float* smt = (float*)wst;
    __syncthreads();
#pragma unroll
    for (int i = 0; i < 4; i++)
#pragma unroll
        for (int j = 0; j < 4; j++)
            smt[(j * 16 + tc) * 68 + tr * 4 + i] = lohi(acc[i][j]);
    __syncthreads();
    for (int u = tid; u < 1024; u += NTHR) {
        int nloc = u >> 4, bq = u & 15;
        int n = nb * 64 + nloc;
        float bias = __ldg(&bih[n]) + __ldg(&bhh[n]);
        float4 v = *(const float4*)&smt[nloc * 68 + bq * 4];
        v.x += bias; v.y += bias; v.z += bias; v.w += bias;
        *(float4*)&g_G0[((size_t)t * 2048 + n) * 64 + bq * 4] = v;
    }
}

// -------- persistent recurrence: tf32 mma --------
__global__ __launch_bounds__(NTHR, 1) void lstm_kernel(
    const float* __restrict__ seq, const int* __restrict__ slen,
    const float* __restrict__ bih, const float* __restrict__ bhh,
    float* __restrict__ out)
{
    extern __shared__ float sb[];
    float* wsm = sb;                   // 24576 floats: permuted weights
    float* xs  = sb + 24576;           // 4 x 4352: stage buffers [b][68]
    float* red = sb + 24576 + 17408;   // 2 x 16 x 66

    const int tid = threadIdx.x, bx = blockIdx.x;
    const int wid = tid >> 5, lane = tid & 31;
    const int kh = wid & 1, bq = wid >> 1;
    const int arow = bq * 16 + (lane >> 2), arow8 = arow + 8;
    const int acol = (lane & 3) * 2;
    const int rc = (lane & 3) * 2, brow = bq * 16 + (lane >> 2);

    // pointwise mapping
    const int pjl = tid >> 6, pb = tid & 63;
    const int pj = bx * 4 + pjl;
    const int gcell = pb * 512 + pj;
    const int kpj = (pj & ~7) | (2 * (pj & 3) + ((pj & 7) >> 2));
    const int mylen = __ldg(&slen[pb]);
    const float b1i = __ldg(&bih[2048 + pj])        + __ldg(&bhh[2048 + pj]);
    const float b1f = __ldg(&bih[2048 + 512 + pj])  + __ldg(&bhh[2048 + 512 + pj]);
    const float b1g = __ldg(&bih[2048 + 1024 + pj]) + __ldg(&bhh[2048 + 1024 + pj]);
    const float b1o = __ldg(&bih[2048 + 1536 + pj]) + __ldg(&bhh[2048 + 1536 + pj]);

    // resident permuted weights -> SMEM
    for (int u = tid; u < 6144; u += NTHR)
        *(float4*)&wsm[u * 4] = __ldg((const float4*)&g_WP[(size_t)bx * 24576 + u * 4]);
    __syncthreads();

#define STG(dstbuf, srcptr, kbase) do { \
    _Pragma("unroll") for (int q = 0; q < 4; q++) { \
        int u_ = q * 256 + tid, bb_ = u_ >> 4, sg_ = u_ & 15; \
        cpa16(&xs[(dstbuf) * 4352 + bb_ * 68 + sg_ * 4], \
              (srcptr) + bb_ * 512 + (kbase) + sg_ * 4); } \
} while (0)

#define STAGE1(c, hf, p) do { STG((hf), g_X1[p], (c) * 64); \
                              STG(2 + (hf), g_H1[(p) ^ 1], (c) * 64); } while (0)
#define STAGE0(c, hf, p) do { STG((hf), g_H0[p], (c) * 64); \
                              STG(2 + (hf), g_H0[p], 256 + (c) * 64); } while (0)

#define COMPR(cc, K8base) do { \
    const float* xb_ = xs + (kh * 2 + ((cc) & 1)) * 4352; \
    const unsigned* wb_ = (const unsigned*)wsm + ((K8base) + (cc) * 8) * 128; \
    _Pragma("unroll") for (int ks2 = 0; ks2 < 8; ks2++) { \
        uint2 a02 = *(const uint2*)&xb_[arow * 68 + ks2 * 8 + acol]; \
        uint2 a13 = *(const uint2*)&xb_[arow8 * 68 + ks2 * 8 + acol]; \
        uint4 bw  = *(const uint4*)&wb_[ks2 * 128 + lane * 4]; \
        MMA(ac0, a02.x, a13.x, a02.y, a13.y, bw.x, bw.y); \
        MMA(ac1, a02.x, a13.x, a02.y, a13.y, bw.z, bw.w); } \
} while (0)

#define RED_STORE() do { \
    __syncthreads(); \
    float* rd_ = red + kh * 1056; \
    rd_[rc * 66 + brow]            = ac0[0]; \
    rd_[(rc + 1) * 66 + brow]      = ac0[1]; \
    rd_[rc * 66 + brow + 8]        = ac0[2]; \
    rd_[(rc + 1) * 66 + brow + 8]  = ac0[3]; \
    rd_[(8 + rc) * 66 + brow]          = ac1[0]; \
    rd_[(8 + rc + 1) * 66 + brow]      = ac1[1]; \
    rd_[(8 + rc) * 66 + brow + 8]      = ac1[2]; \
    rd_[(8 + rc + 1) * 66 + brow + 8]  = ac1[3]; \
    __syncthreads(); \
} while (0)

#define GAT(g) (red[((g) * 4 + pjl) * 66 + pb] + red[1056 + ((g) * 4 + pjl) * 66 + pb])

    float c0 = 0.f, c1 = 0.f, h0reg = 0.f, h1reg = 0.f, x1reg = 0.f;
    unsigned ph = 0;

    // ---- prologue: pw0(0), gemm0 term is zero ----
    {
        size_t gp = ((size_t)0 * 2048 + pj) * 64 + pb;
        float gi = __ldg(&g_G0[gp]);
        float gf = __ldg(&g_G0[gp + 32768]);
        float gg = __ldg(&g_G0[gp + 65536]);
        float go = __ldg(&g_G0[gp + 98304]);
        float cs = sigf(gf) * c0 + sigf(gi) * tanhf(gg);
        float hs = sigf(go) * tanhf(cs);
        c0 = cs; h0reg = hs;          // t=0 < mylen always
        __stcg(&g_H0[0][pb * 512 + kpj], tf32r(h0reg));
        float xv = __ldg(&seq[((size_t)pb * 1024 + 0) * 512 + pj]);
        x1reg = hs + xv;
        __stcg(&g_X1[0][pb * 512 + kpj], tf32r(x1reg));
    }
    gbar(ph);

#pragma unroll 1
    for (int t = 0; t < 1024; t++) {
        const int p = t & 1;
        // prefetch G0(t+1) and seq(t+1)
        int t1 = (t < 1023) ? t + 1 : t;
        size_t gp = ((size_t)t1 * 2048 + pj) * 64 + pb;
        float p0 = __ldg(&g_G0[gp]);
        float p1 = __ldg(&g_G0[gp + 32768]);
        float p2 = __ldg(&g_G0[gp + 65536]);
        float p3 = __ldg(&g_G0[gp + 98304]);
        float xvp = __ldg(&seq[((size_t)pb * 1024 + t1) * 512 + pj]);

        // ===== gemm1(t) =====
        float ac0[4] = {0, 0, 0, 0}, ac1[4] = {0, 0, 0, 0};
        STAGE1(0, 0, p); CPCOMMIT;
#pragma unroll 1
        for (int cc = 0; cc < 8; cc++) {
            CPWAIT; __syncthreads();
            if (cc < 7)        { STAGE1(cc + 1, (cc + 1) & 1, p); CPCOMMIT; }
            else if (t < 1023) { STAGE0(0, 0, p);                 CPCOMMIT; }
            COMPR(cc, kh * 64);
        }
        RED_STORE();
        // ===== pw1(t) =====
        {
            float gi = GAT(0) + b1i, gf = GAT(1) + b1f;
            float gg = GAT(2) + b1g, go = GAT(3) + b1o;
            float cs = sigf(gf) * c1 + sigf(gi) * tanhf(gg);
            float hs = sigf(go) * tanhf(cs);
            bool act = t < mylen;
            out[((size_t)pb * 1024 + t) * 512 + pj] = act ? (hs + x1reg) : 0.f;
            if (act) { c1 = cs; h1reg = hs; }
            __stcg(&g_H1[p][pb * 512 + kpj], tf32r(h1reg));
        }
        if (t == 1023) break;
        // ===== gemm0(t+1) =====
        ac0[0] = ac0[1] = ac0[2] = ac0[3] = 0.f;
        ac1[0] = ac1[1] = ac1[2] = ac1[3] = 0.f;
#pragma unroll 1
        for (int cc = 0; cc < 4; cc++) {
            CPWAIT; __syncthreads();
            if (cc < 3) { STAGE0(cc + 1, (cc + 1) & 1, p); CPCOMMIT; }
            COMPR(cc, 128 + kh * 32);
        }
        RED_STORE();
        // ===== pw0(t+1) =====
        {
            float gi = p0 + GAT(0), gf = p1 + GAT(1);
            float gg = p2 + GAT(2), go = p3 + GAT(3);
            float cs = sigf(gf) * c0 + sigf(gi) * tanhf(gg);
            float hs = sigf(go) * tanhf(cs);
            if (t1 < mylen) { c0 = cs; h0reg = hs; }
            __stcg(&g_H0[p ^ 1][pb * 512 + kpj], tf32r(h0reg));
            x1reg = hs + xvp;
            __stcg(&g_X1[p ^ 1][pb * 512 + kpj], tf32r(x1reg));
        }
        gbar(ph);
    }

    // ---- tail: final h, c ----
    const size_t HO = (size_t)64 * 1024 * 512;
    out[HO + gcell]         = h0reg;
    out[HO + 32768 + gcell] = h1reg;
    out[HO + 65536 + gcell] = c0;
    out[HO + 98304 + gcell] = c1;
}

extern "C" void kernel_launch(void* const* d_in, const int* in_sizes, int n_in,
                              void* d_out, int out_size) {
    const float* seq  = (const float*)d_in[0];
    const int*   slen = (const int*)d_in[1];
    const float* Wih  = (const float*)d_in[2];
    const float* Whh  = (const float*)d_in[3];
    const float* bih  = (const float*)d_in[4];
    const float* bhh  = (const float*)d_in[5];
    float* out = (float*)d_out;

    init_kernel<<<128, 256>>>();
    g0_kernel<<<dim3(32, 1024), NTHR>>>(seq, Wih, bih, bhh);
    wprep_kernel<<<NCTA, NTHR>>>(Wih, Whh);

    const int smem = (24576 + 17408 + 2112) * 4;   // 176384 B
    cudaFuncSetAttribute(lstm_kernel, cudaFuncAttributeMaxDynamicSharedMemorySize, smem);
    lstm_kernel<<<NCTA, NTHR, smem>>>(seq, slen, bih, bhh, out);
}

// round 15
// speedup vs baseline: 3.4510x; 1.1934x over previous
#include <cuda_runtime.h>
#include <cstdint>

#define NCTA 128
#define NTHR 512
#define GTHR 256
typedef unsigned long long ull;

// -------- device scratch --------
__device__ __align__(128) float g_G0[(size_t)1024 * 2048 * 64];  // [t][n][b] fp32 exact
// recurrent activations, chunked + swizzled, tf32-rounded:
// X1/H1: [chunk(8)][b(64)][64 floats swizzled], H0: [chunk(4)][b(64)][128 floats swizzled]
__device__ __align__(128) float g_X1[2][64 * 512];
__device__ __align__(128) float g_H1[2][64 * 512];
__device__ __align__(128) float g_H0[2][64 * 512];
__device__ __align__(128) float g_WP[(size_t)NCTA * 192 * 128];  // permuted tf32 weights
__device__ unsigned g_bar;

#define FMA2(d, a, b) asm("fma.rn.f32x2 %0, %1, %2, %0;" : "+l"(d) : "l"(a), "l"(b))

#define MMA(d, a0, a1, a2, a3, b0, b1) \
    asm("mma.sync.aligned.m16n8k8.row.col.f32.tf32.tf32.f32 " \
        "{%0,%1,%2,%3}, {%4,%5,%6,%7}, {%8,%9}, {%0,%1,%2,%3};" \
        : "+f"(d[0]), "+f"(d[1]), "+f"(d[2]), "+f"(d[3]) \
        : "r"(a0), "r"(a1), "r"(a2), "r"(a3), "r"(b0), "r"(b1))

__device__ __forceinline__ float lohi(ull v) {
    return __uint_as_float((unsigned)v) + __uint_as_float((unsigned)(v >> 32));
}
__device__ __forceinline__ float sigf(float x) { return 1.f / (1.f + __expf(-x)); }
__device__ __forceinline__ float tf32r(float x) {
    unsigned u; asm("cvt.rna.tf32.f32 %0, %1;" : "=r"(u) : "f"(x));
    return __uint_as_float(u);
}
// float4-group XOR swizzle within a row (row length 64 or 128 floats)
__device__ __forceinline__ int swz(int off, int b) {
    return ((((off >> 2) ^ (b & 15)) << 2) | (off & 3));
}

__device__ __forceinline__ unsigned s2u(const void* p) {
    return (unsigned)__cvta_generic_to_shared(p);
}
__device__ __forceinline__ void mbar_init(ull* m, unsigned cnt) {
    asm volatile("mbarrier.init.shared.b64 [%0], %1;" :: "r"(s2u(m)), "r"(cnt) : "memory");
}
__device__ __forceinline__ void mbar_expect(ull* m, unsigned bytes) {
    asm volatile("mbarrier.arrive.expect_tx.shared.b64 _, [%0], %1;"
                 :: "r"(s2u(m)), "r"(bytes) : "memory");
}
__device__ __forceinline__ void mbar_wait(ull* m, unsigned par) {
    asm volatile("{\n\t.reg .pred P;\nLW%=:\n\t"
                 "mbarrier.try_wait.parity.shared.b64 P, [%0], %1;\n\t"
                 "@!P bra LW%=;\n\t}"
                 :: "r"(s2u(m)), "r"(par) : "memory");
}
__device__ __forceinline__ void bulk_cp(float* d, const float* s, unsigned bytes, ull* m) {
    asm volatile("cp.async.bulk.shared::cluster.global.mbarrier::complete_tx::bytes "
                 "[%0], [%1], %2, [%3];"
                 :: "r"(s2u(d)), "l"(s), "r"(bytes), "r"(s2u(m)) : "memory");
}

__device__ __forceinline__ void gbar(unsigned& ph) {
    asm volatile("fence.proxy.async;" ::: "memory");
    __syncthreads();
    ph += NCTA;
    if (threadIdx.x == 0) {
        __threadfence();
        atomicAdd(&g_bar, 1u);
        while (*(volatile unsigned*)&g_bar < ph) { }
        __threadfence();
    }
    __syncthreads();
}

__global__ void init_kernel() {
    int i = blockIdx.x * blockDim.x + threadIdx.x;
    if (i == 0) g_bar = 0;
    if (i < 64 * 512) { g_H1[0][i] = 0.f; g_H1[1][i] = 0.f; }
}

// -------- permute weights into mma B-fragment order, tf32-rounded --------
__global__ __launch_bounds__(GTHR) void wprep_kernel(
    const float* __restrict__ Wih, const float* __restrict__ Whh)
{
    int bx = blockIdx.x;
    for (int idx = threadIdx.x; idx < 192 * 128; idx += GTHR) {
        int K8 = idx >> 7, li = idx & 127;
        int lane = li >> 2, q = li & 3;
        int nt = q >> 1, breg = q & 1;
        int r = nt * 8 + (lane >> 2);
        int kin = (lane & 3) + breg * 4;
        int nglob = (r >> 2) * 512 + bx * 4 + (r & 3);
        const float* src;
        if (K8 < 64)       src = &Wih[(size_t)(2048 + nglob) * 512 + K8 * 8 + kin];
        else if (K8 < 128) src = &Whh[(size_t)(2048 + nglob) * 512 + (K8 - 64) * 8 + kin];
        else               src = &Whh[(size_t)nglob * 512 + (K8 - 128) * 8 + kin];
        g_WP[(size_t)bx * 24576 + idx] = tf32r(__ldg(src));
    }
}

// -------- G0[t][n][b] = (seq @ W_ih0^T)(b,n) + biases  (exact fp32) --------
__global__ __launch_bounds__(GTHR) void g0_kernel(
    const float* __restrict__ seq, const float* __restrict__ Wih,
    const float* __restrict__ bih, const float* __restrict__ bhh)
{
    __shared__ float  xs[64 * 68];
    __shared__ float2 wst[32 * 66 + 64];
    const int t = blockIdx.y, nb = blockIdx.x;
    const int tid = threadIdx.x, tr = tid >> 4, tc = tid & 15;
    ull acc[4][4] = {};
    for (int kc = 0; kc < 8; kc++) {
        __syncthreads();
#pragma unroll
        for (int i = 0; i < 4; i++) {
            int s = i * 256 + tid, rr = s >> 4, c4 = s & 15;
            *(float4*)&xs[rr * 68 + c4 * 4] =
                *(const float4*)&seq[((size_t)rr * 1024 + t) * 512 + kc * 64 + c4 * 4];
            float4 wv = __ldg((const float4*)&Wih[((size_t)(nb * 64 + rr)) * 512 + kc * 64 + c4 * 4]);
            wst[(c4 * 2) * 66 + rr]     = make_float2(wv.x, wv.y);
            wst[(c4 * 2 + 1) * 66 + rr] = make_float2(wv.z, wv.w);
        }
        __syncthreads();
        const ull* wstu = (const ull*)wst;
#pragma unroll 4
        for (int k2 = 0; k2 < 32; k2++) {
            ull xr[4], wr[4];
#pragma unroll
            for (int i = 0; i < 4; i++) xr[i] = *(const ull*)&xs[(tr * 4 + i) * 68 + k2 * 2];
#pragma unroll
            for (int j = 0; j < 4; j++) wr[j] = wstu[k2 * 66 + j * 16 + tc];
#pragma unroll
            for (int i = 0; i < 4; i++)
#pragma unroll
                for (int j = 0; j < 4; j++) FMA2(acc[i][j], xr[i], wr[j]);
        }
    }
    float* smt = (float*)wst;
    __syncthreads();
#pragma unroll
    for (int i = 0; i < 4; i++)
#pragma unroll
        for (int j = 0; j < 4; j++)
            smt[(j * 16 + tc) * 68 + tr * 4 + i] = lohi(acc[i][j]);
    __syncthreads();
    for (int u = tid; u < 1024; u += GTHR) {
        int nloc = u >> 4, bq = u & 15;
        int n = nb * 64 + nloc;
        float bias = __ldg(&bih[n]) + __ldg(&bhh[n]);
        float4 v = *(const float4*)&smt[nloc * 68 + bq * 4];
        v.x += bias; v.y += bias; v.z += bias; v.w += bias;
        *(float4*)&g_G0[((size_t)t * 2048 + n) * 64 + bq * 4] = v;
    }
}

// -------- persistent recurrence: tf32 mma + bulk-copy ring --------
__global__ __launch_bounds__(NTHR, 1) void lstm_kernel(
    const float* __restrict__ seq, const int* __restrict__ slen,
    const float* __restrict__ bih, const float* __restrict__ bhh,
    float* __restrict__ out)
{
    extern __shared__ float sb[];
    float* wsm = sb;               // 24576 floats: permuted weights
    float* stg = sb + 24576;       // 3 x 8192: bulk stage slots
    float* red = sb + 49152;       // 4 x 16 x 66
    __shared__ ull mb[3];

    const int tid = threadIdx.x, bx = blockIdx.x;
    const int wid = tid >> 5, lane = tid & 31;
    const int kq = wid >> 2, bq = wid & 3;
    const int arow = bq * 16 + (lane >> 2), arow8 = arow + 8;
    const int acol = (lane & 3) * 2;
    const int rc = (lane & 3) * 2, brow = bq * 16 + (lane >> 2);

    // pointwise mapping (first 256 threads)
    const bool ispw = tid < 256;
    const int pjl = (tid >> 6) & 3, pb = tid & 63;
    const int pj = bx * 4 + pjl;
    const int gcell = pb * 512 + pj;
    const int kpj = (pj & ~7) | (2 * (pj & 3) + ((pj & 7) >> 2));
    const int xh_addr = (kpj >> 6) * 4096 + pb * 64 + swz(kpj & 63, pb);
    const int h0_addr = (kpj >> 7) * 8192 + pb * 128 + swz(kpj & 127, pb);
    const int mylen = __ldg(&slen[pb]);
    const float b1i = __ldg(&bih[2048 + pj])        + __ldg(&bhh[2048 + pj]);
    const float b1f = __ldg(&bih[2048 + 512 + pj])  + __ldg(&bhh[2048 + 512 + pj]);
    const float b1g = __ldg(&bih[2048 + 1024 + pj]) + __ldg(&bhh[2048 + 1024 + pj]);
    const float b1o = __ldg(&bih[2048 + 1536 + pj]) + __ldg(&bhh[2048 + 1536 + pj]);

    // resident permuted weights -> SMEM
    for (int u = tid; u < 6144; u += NTHR)
        *(float4*)&wsm[u * 4] = __ldg((const float4*)&g_WP[(size_t)bx * 24576 + u * 4]);
    if (tid == 0) { mbar_init(&mb[0], 1); mbar_init(&mb[1], 1); mbar_init(&mb[2], 1); }
    __syncthreads();

#define ISSUE(cc) do { if (tid == 0) { int sl_ = (cc) % 3; \
    mbar_expect(&mb[sl_], 32768u); \
    if ((cc) < 8) { \
        bulk_cp(stg + sl_ * 8192,        xsrc + (cc) * 4096, 16384u, &mb[sl_]); \
        bulk_cp(stg + sl_ * 8192 + 4096, hsrc + (cc) * 4096, 16384u, &mb[sl_]); \
    } else { \
        bulk_cp(stg + sl_ * 8192, h0src + ((cc) - 8) * 8192, 32768u, &mb[sl_]); \
    } } } while (0)

#define COMP1(cc, sl) do { \
    const float* slab_ = stg + (sl) * 8192 + ((kq >= 2) ? 4096 : 0); \
    const unsigned* wb_ = (const unsigned*)wsm + \
        ((((kq < 2) ? ((cc) * 8) : (64 + (cc) * 8)) + (kq & 1) * 4)) * 128; \
    _Pragma("unroll") for (int i = 0; i < 4; i++) { \
        int off_ = ((kq & 1) * 4 + i) * 8 + acol; \
        uint2 a02 = *(const uint2*)(slab_ + arow * 64 + swz(off_, arow)); \
        uint2 a13 = *(const uint2*)(slab_ + arow8 * 64 + swz(off_, arow8)); \
        uint4 bw = *(const uint4*)(wb_ + i * 128 + lane * 4); \
        MMA(ac0, a02.x, a13.x, a02.y, a13.y, bw.x, bw.y); \
        MMA(ac1, a02.x, a13.x, a02.y, a13.y, bw.z, bw.w); } \
} while (0)

#define COMP0(c8, sl) do { \
    const float* slab_ = stg + (sl) * 8192; \
    const unsigned* wb_ = (const unsigned*)wsm + (128 + (c8) * 16 + kq * 4) * 128; \
    _Pragma("unroll") for (int i = 0; i < 4; i++) { \
        int off_ = (kq * 4 + i) * 8 + acol; \
        uint2 a02 = *(const uint2*)(slab_ + arow * 128 + swz(off_, arow)); \
        uint2 a13 = *(const uint2*)(slab_ + arow8 * 128 + swz(off_, arow8)); \
        uint4 bw = *(const uint4*)(wb_ + i * 128 + lane * 4); \
        MMA(ac0, a02.x, a13.x, a02.y, a13.y, bw.x, bw.y); \
        MMA(ac1, a02.x, a13.x, a02.y, a13.y, bw.z, bw.w); } \
} while (0)

#define RED_STORE() do { \
    __syncthreads(); \
    float* rd_ = red + kq * 1056; \
    rd_[rc * 66 + brow]                = ac0[0]; \
    rd_[(rc + 1) * 66 + brow]          = ac0[1]; \
    rd_[rc * 66 + brow + 8]            = ac0[2]; \
    rd_[(rc + 1) * 66 + brow + 8]      = ac0[3]; \
    rd_[(8 + rc) * 66 + brow]          = ac1[0]; \
    rd_[(8 + rc + 1) * 66 + brow]      = ac1[1]; \
    rd_[(8 + rc) * 66 + brow + 8]      = ac1[2]; \
    rd_[(8 + rc + 1) * 66 + brow + 8]  = ac1[3]; \
    __syncthreads(); \
} while (0)

#define GAT(g) (red[((g) * 4 + pjl) * 66 + pb] + red[1056 + ((g) * 4 + pjl) * 66 + pb] + \
                red[2112 + ((g) * 4 + pjl) * 66 + pb] + red[3168 + ((g) * 4 + pjl) * 66 + pb])

    float c0 = 0.f, c1 = 0.f, h0reg = 0.f, h1reg = 0.f, x1reg = 0.f;
    unsigned ph = 0;

    // ---- prologue: pw0(0); gemm0 term is zero (h0(-1)=0) ----
    if (ispw) {
        size_t gp = (size_t)pj * 64 + pb;
        float gi = __ldg(&g_G0[gp]);
        float gf = __ldg(&g_G0[gp + 32768]);
        float gg = __ldg(&g_G0[gp + 65536]);
        float go = __ldg(&g_G0[gp + 98304]);
        float cs = sigf(gf) * c0 + sigf(gi) * tanhf(gg);
        float hs = sigf(go) * tanhf(cs);
        c0 = cs; h0reg = hs;                    // t=0 < mylen always
        __stcg(&g_H0[0][h0_addr], tf32r(h0reg));
        float xv = __ldg(&seq[(size_t)pb * 1024 * 512 + pj]);
        x1reg = hs + xv;
        __stcg(&g_X1[0][xh_addr], tf32r(x1reg));
    }
    gbar(ph);

#pragma unroll 1
    for (int t = 0; t < 1024; t++) {
        const int p = t & 1;
        const float* xsrc  = g_X1[p];
        const float* hsrc  = g_H1[p ^ 1];
        const float* h0src = g_H0[p];

        // prefetch G0(t+1), seq(t+1)
        int t1 = (t < 1023) ? t + 1 : t;
        size_t gp = ((size_t)t1 * 2048 + pj) * 64 + pb;
        float p0 = __ldg(&g_G0[gp]);
        float p1 = __ldg(&g_G0[gp + 32768]);
        float p2 = __ldg(&g_G0[gp + 65536]);
        float p3 = __ldg(&g_G0[gp + 98304]);
        float xvp = __ldg(&seq[((size_t)pb * 1024 + t1) * 512 + pj]);

        ISSUE(0); ISSUE(1);
        float ac0[4] = {0, 0, 0, 0}, ac1[4] = {0, 0, 0, 0};

        // ===== gemm1(t): [X1(t); H1(t-1)] =====
#pragma unroll
        for (int cc = 0; cc < 8; cc++) {
            if (tid == 0) mbar_wait(&mb[cc % 3], (cc / 3) & 1);
            __syncthreads();
            if (cc < 6)        ISSUE(cc + 2);
            else if (t < 1023) ISSUE(cc + 2);
            COMP1(cc, cc % 3);
        }
        RED_STORE();
        // ===== pw1(t) =====
        if (ispw) {
            float gi = GAT(0) + b1i, gf = GAT(1) + b1f;
            float gg = GAT(2) + b1g, go = GAT(3) + b1o;
            float cs = sigf(gf) * c1 + sigf(gi) * tanhf(gg);
            float hs = sigf(go) * tanhf(cs);
            bool act = t < mylen;
            out[((size_t)pb * 1024 + t) * 512 + pj] = act ? (hs + x1reg) : 0.f;
            if (act) { c1 = cs; h1reg = hs; }
            __stcg(&g_H1[p][xh_addr], tf32r(h1reg));
        }
        if (t == 1023) break;

        // ===== gemm0(t+1): H0(t) @ Whh0^T =====
        ac0[0] = ac0[1] = ac0[2] = ac0[3] = 0.f;
        ac1[0] = ac1[1] = ac1[2] = ac1[3] = 0.f;
#pragma unroll
        for (int cc = 8; cc < 12; cc++) {
            if (tid == 0) mbar_wait(&mb[cc % 3], (cc / 3) & 1);
            __syncthreads();
            if (cc < 10) ISSUE(cc + 2);
            COMP0(cc - 8, cc % 3);
        }
        RED_STORE();
        // ===== pw0(t+1) =====
        if (ispw) {
            float gi = p0 + GAT(0), gf = p1 + GAT(1);
            float gg = p2 + GAT(2), go = p3 + GAT(3);
            float cs = sigf(gf) * c0 + sigf(gi) * tanhf(gg);
            float hs = sigf(go) * tanhf(cs);
            if (t1 < mylen) { c0 = cs; h0reg = hs; }
            __stcg(&g_H0[p ^ 1][h0_addr], tf32r(h0reg));
            x1reg = hs + xvp;
            __stcg(&g_X1[p ^ 1][xh_addr], tf32r(x1reg));
        }
        gbar(ph);
    }

    // ---- tail: final h, c ----
    if (ispw) {
        const size_t HO = (size_t)64 * 1024 * 512;
        out[HO + gcell]         = h0reg;
        out[HO + 32768 + gcell] = h1reg;
        out[HO + 65536 + gcell] = c0;
        out[HO + 98304 + gcell] = c1;
    }
}

extern "C" void kernel_launch(void* const* d_in, const int* in_sizes, int n_in,
                              void* d_out, int out_size) {
    const float* seq  = (const float*)d_in[0];
    const int*   slen = (const int*)d_in[1];
    const float* Wih  = (const float*)d_in[2];
    const float* Whh  = (const float*)d_in[3];
    const float* bih  = (const float*)d_in[4];
    const float* bhh  = (const float*)d_in[5];
    float* out = (float*)d_out;

    init_kernel<<<128, 256>>>();
    g0_kernel<<<dim3(32, 1024), GTHR>>>(seq, Wih, bih, bhh);
    wprep_kernel<<<NCTA, GTHR>>>(Wih, Whh);

    const int smem = (24576 + 3 * 8192 + 4224) * 4;   // 213504 B
    cudaFuncSetAttribute(lstm_kernel, cudaFuncAttributeMaxDynamicSharedMemorySize, smem);
    lstm_kernel<<<NCTA, NTHR, smem>>>(seq, slen, bih, bhh, out);
}

// round 16
// speedup vs baseline: 3.4661x; 1.0044x over previous
#include <cuda_runtime.h>
#include <cstdint>

#define NCTA 128
#define NTHR 512
#define GTHR 256
typedef unsigned long long ull;

// -------- device scratch --------
__device__ __align__(128) float g_G0[(size_t)1024 * 2048 * 64];  // [t][n][b] fp32 exact
// recurrent activations, chunked (4 x [64b][128k], swizzled), tf32-rounded:
__device__ __align__(128) float g_X1R[2][64 * 512];
__device__ __align__(128) float g_H1R[2][64 * 512];
__device__ __align__(128) float g_H0R[2][64 * 512];
__device__ __align__(128) float g_X1E[2][64 * 512];   // exact X1, plain [b][j]
__device__ __align__(128) float g_WPA[(size_t)64 * 32768];  // gemm1 weights, frag order
__device__ __align__(128) float g_WPB[(size_t)64 * 16384];  // gemm0 weights
__device__ unsigned g_bar;

#define FMA2(d, a, b) asm("fma.rn.f32x2 %0, %1, %2, %0;" : "+l"(d) : "l"(a), "l"(b))

#define MMA(d, a0, a1, a2, a3, b0, b1) \
    asm("mma.sync.aligned.m16n8k8.row.col.f32.tf32.tf32.f32 " \
        "{%0,%1,%2,%3}, {%4,%5,%6,%7}, {%8,%9}, {%0,%1,%2,%3};" \
        : "+f"(d[0]), "+f"(d[1]), "+f"(d[2]), "+f"(d[3]) \
        : "r"(a0), "r"(a1), "r"(a2), "r"(a3), "r"(b0), "r"(b1))

__device__ __forceinline__ float lohi(ull v) {
    return __uint_as_float((unsigned)v) + __uint_as_float((unsigned)(v >> 32));
}
__device__ __forceinline__ float sigf(float x) { return 1.f / (1.f + __expf(-x)); }
__device__ __forceinline__ float tf32r(float x) {
    unsigned u; asm("cvt.rna.tf32.f32 %0, %1;" : "=r"(u) : "f"(x));
    return __uint_as_float(u);
}
__device__ __forceinline__ int swz(int off, int b) {
    return ((((off >> 2) ^ (b & 15)) << 2) | (off & 3));
}
__device__ __forceinline__ unsigned s2u(const void* p) {
    return (unsigned)__cvta_generic_to_shared(p);
}
__device__ __forceinline__ void mbar_init(ull* m, unsigned cnt) {
    asm volatile("mbarrier.init.shared.b64 [%0], %1;" :: "r"(s2u(m)), "r"(cnt) : "memory");
}
__device__ __forceinline__ void mbar_expect(ull* m, unsigned bytes) {
    asm volatile("mbarrier.arrive.expect_tx.shared.b64 _, [%0], %1;"
                 :: "r"(s2u(m)), "r"(bytes) : "memory");
}
__device__ __forceinline__ void mbar_arrive(ull* m) {
    asm volatile("mbarrier.arrive.shared.b64 _, [%0];" :: "r"(s2u(m)) : "memory");
}
__device__ __forceinline__ void mbar_wait(ull* m, unsigned par) {
    asm volatile("{\n\t.reg .pred P;\nLW%=:\n\t"
                 "mbarrier.try_wait.parity.shared.b64 P, [%0], %1;\n\t"
                 "@!P bra LW%=;\n\t}"
                 :: "r"(s2u(m)), "r"(par) : "memory");
}
__device__ __forceinline__ void bulk_cp(float* d, const float* s, unsigned bytes, ull* m) {
    asm volatile("cp.async.bulk.shared::cluster.global.mbarrier::complete_tx::bytes "
                 "[%0], [%1], %2, [%3];"
                 :: "r"(s2u(d)), "l"(s), "r"(bytes), "r"(s2u(m)) : "memory");
}

__device__ __forceinline__ void gbar(unsigned& ph) {
    asm volatile("fence.proxy.async;" ::: "memory");
    __syncthreads();
    ph += NCTA;
    if (threadIdx.x == 0) {
        __threadfence();
        atomicAdd(&g_bar, 1u);
        while (*(volatile unsigned*)&g_bar < ph) { }
        __threadfence();
    }
    __syncthreads();
}

__global__ void init_kernel() {
    int i = blockIdx.x * blockDim.x + threadIdx.x;
    if (i == 0) g_bar = 0;
    if (i < 64 * 512) { g_H1R[0][i] = 0.f; g_H1R[1][i] = 0.f; }
}

// -------- permute weights into mma B-fragment order, tf32-rounded --------
__global__ __launch_bounds__(GTHR) void wprep_kernel(
    const float* __restrict__ Wih, const float* __restrict__ Whh)
{
    int bx = blockIdx.x;
    if (bx < 64) {
        for (int idx = threadIdx.x; idx < 32768; idx += GTHR) {
            int K8 = idx >> 8, rem = idx & 255;
            int nh = rem >> 7, li = rem & 127;
            int lane = li >> 2, q = li & 3, nt = q >> 1, breg = q & 1;
            int r32 = nh * 16 + nt * 8 + (lane >> 2);
            int n1 = 2048 + (r32 >> 3) * 512 + bx * 8 + (r32 & 7);
            int kk = K8 * 8 + (lane & 3) + breg * 4;
            const float* src = (kk < 512) ? &Wih[(size_t)n1 * 512 + kk]
                                          : &Whh[(size_t)n1 * 512 + kk - 512];
            g_WPA[(size_t)bx * 32768 + idx] = tf32r(__ldg(src));
        }
    } else {
        int bxg = bx - 64;
        for (int idx = threadIdx.x; idx < 16384; idx += GTHR) {
            int K8 = idx >> 8, rem = idx & 255;
            int nh = rem >> 7, li = rem & 127;
            int lane = li >> 2, q = li & 3, nt = q >> 1, breg = q & 1;
            int r32 = nh * 16 + nt * 8 + (lane >> 2);
            int n0 = (r32 >> 3) * 512 + bxg * 8 + (r32 & 7);
            int kk = K8 * 8 + (lane & 3) + breg * 4;
            g_WPB[(size_t)bxg * 16384 + idx] = tf32r(__ldg(&Whh[(size_t)n0 * 512 + kk]));
        }
    }
}

// -------- G0[t][n][b] = (seq @ W_ih0^T)(b,n) + biases  (exact fp32) --------
__global__ __launch_bounds__(GTHR) void g0_kernel(
    const float* __restrict__ seq, const float* __restrict__ Wih,
    const float* __restrict__ bih, const float* __restrict__ bhh)
{
    __shared__ float  xs[64 * 68];
    __shared__ float2 wst[32 * 66 + 64];
    const int t = blockIdx.y, nb = blockIdx.x;
    const int tid = threadIdx.x, tr = tid >> 4, tc = tid & 15;
    ull acc[4][4] = {};
    for (int kc = 0; kc < 8; kc++) {
        __syncthreads();
#pragma unroll
        for (int i = 0; i < 4; i++) {
            int s = i * 256 + tid, rr = s >> 4, c4 = s & 15;
            *(float4*)&xs[rr * 68 + c4 * 4] =
                *(const float4*)&seq[((size_t)rr * 1024 + t) * 512 + kc * 64 + c4 * 4];
            float4 wv = __ldg((const float4*)&Wih[((size_t)(nb * 64 + rr)) * 512 + kc * 64 + c4 * 4]);
            wst[(c4 * 2) * 66 + rr]     = make_float2(wv.x, wv.y);
            wst[(c4 * 2 + 1) * 66 + rr] = make_float2(wv.z, wv.w);
        }
        __syncthreads();
        const ull* wstu = (const ull*)wst;
#pragma unroll 4
        for (int k2 = 0; k2 < 32; k2++) {
            ull xr[4], wr[4];
#pragma unroll
            for (int i = 0; i < 4; i++) xr[i] = *(const ull*)&xs[(tr * 4 + i) * 68 + k2 * 2];
#pragma unroll
            for (int j = 0; j < 4; j++) wr[j] = wstu[k2 * 66 + j * 16 + tc];
#pragma unroll
            for (int i = 0; i < 4; i++)
#pragma unroll
                for (int j = 0; j < 4; j++) FMA2(acc[i][j], xr[i], wr[j]);
        }
    }
    float* smt = (float*)wst;
    __syncthreads();
#pragma unroll
    for (int i = 0; i < 4; i++)
#pragma unroll
        for (int j = 0; j < 4; j++)
            smt[(j * 16 + tc) * 68 + tr * 4 + i] = lohi(acc[i][j]);
    __syncthreads();
    for (int u = tid; u < 1024; u += GTHR) {
        int nloc = u >> 4, bq = u & 15;
        int n = nb * 64 + nloc;
        float bias = __ldg(&bih[n]) + __ldg(&bhh[n]);
        float4 v = *(const float4*)&smt[nloc * 68 + bq * 4];
        v.x += bias; v.y += bias; v.z += bias; v.w += bias;
        *(float4*)&g_G0[((size_t)t * 2048 + n) * 64 + bq * 4] = v;
    }
}

// -------- persistent recurrence: split CTA groups, tf32 mma, mbarrier ring --------
__global__ __launch_bounds__(NTHR, 1) void lstm_kernel(
    const float* __restrict__ seq, const int* __restrict__ slen,
    const float* __restrict__ bih, const float* __restrict__ bhh,
    float* __restrict__ out)
{
    extern __shared__ float sb[];
    float* wsm = sb;             // A: 32768 floats, B: 16384
    float* stg = sb + 32768;     // 2 x 8192 stage slots
    float* red = sb + 49152;     // [kh 2][n32][66]
    __shared__ ull mbf[2], mbe[2];

    const int tid = threadIdx.x, bx = blockIdx.x;
    const bool isA = bx < 64;
    const int bxg = isA ? bx : bx - 64;
    const int lane = tid & 31, wid = tid >> 5;
    const int bq = wid & 3, nh = (wid >> 2) & 1, kh = wid >> 3;
    const int arow = bq * 16 + (lane >> 2), arow8 = arow + 8;
    const int acol = (lane & 3) * 2;
    const int rc = (lane & 3) * 2, brow = arow;

    // pointwise mapping: cell (pb, pj)
    const int pjl = tid >> 6, pb = tid & 63;
    const int pj = bxg * 8 + pjl;
    const int gcell = pb * 512 + pj;
    const int kpj = (pj & ~7) | (2 * (pj & 3) + ((pj & 7) >> 2));
    const int ch_addr = (kpj >> 7) * 8192 + pb * 128 + swz(kpj & 127, pb);
    const int mylen = __ldg(&slen[pb]);
    const float b1i = __ldg(&bih[2048 + pj])        + __ldg(&bhh[2048 + pj]);
    const float b1f = __ldg(&bih[2048 + 512 + pj])  + __ldg(&bhh[2048 + 512 + pj]);
    const float b1g = __ldg(&bih[2048 + 1024 + pj]) + __ldg(&bhh[2048 + 1024 + pj]);
    const float b1o = __ldg(&bih[2048 + 1536 + pj]) + __ldg(&bhh[2048 + 1536 + pj]);

    // resident weights -> SMEM
    {
        const float* wsrc = isA ? &g_WPA[(size_t)bxg * 32768] : &g_WPB[(size_t)bxg * 16384];
        int nf4 = isA ? 8192 : 4096;
        for (int u = tid; u < nf4; u += NTHR)
            *(float4*)&wsm[u * 4] = __ldg((const float4*)&wsrc[u * 4]);
    }
    if (tid == 0) {
        mbar_init(&mbf[0], 1);  mbar_init(&mbf[1], 1);
        mbar_init(&mbe[0], 16); mbar_init(&mbe[1], 16);
    }
    __syncthreads();

#define COMPX(K8base, sl) do { \
    const float* slab_ = stg + (sl) * 8192; \
    const unsigned* wu_ = (const unsigned*)wsm; \
    _Pragma("unroll") for (int i = 0; i < 8; i++) { \
        int off_ = (kh * 8 + i) * 8 + acol; \
        uint2 a02 = *(const uint2*)(slab_ + arow * 128 + swz(off_, arow)); \
        uint2 a13 = *(const uint2*)(slab_ + arow8 * 128 + swz(off_, arow8)); \
        int K8_ = (K8base) + kh * 8 + i; \
        uint4 bw = *(const uint4*)(wu_ + (K8_ * 2 + nh) * 128 + lane * 4); \
        MMA(ac0, a02.x, a13.x, a02.y, a13.y, bw.x, bw.y); \
        MMA(ac1, a02.x, a13.x, a02.y, a13.y, bw.z, bw.w); \
    } } while (0)

#define RED_STORE() do { \
    __syncthreads(); \
    float* rd_ = red + kh * 2112 + nh * 1056; \
    rd_[rc * 66 + brow]                = ac0[0]; \
    rd_[(rc + 1) * 66 + brow]          = ac0[1]; \
    rd_[rc * 66 + brow + 8]            = ac0[2]; \
    rd_[(rc + 1) * 66 + brow + 8]      = ac0[3]; \
    rd_[(8 + rc) * 66 + brow]          = ac1[0]; \
    rd_[(8 + rc + 1) * 66 + brow]      = ac1[1]; \
    rd_[(8 + rc) * 66 + brow + 8]      = ac1[2]; \
    rd_[(8 + rc + 1) * 66 + brow + 8]  = ac1[3]; \
    __syncthreads(); \
} while (0)

#define GAT(g) (red[((g) * 8 + pjl) * 66 + pb] + red[2112 + ((g) * 8 + pjl) * 66 + pb])

#define ISSUE_A(cc) do { int s2_ = (cc) & 1; \
    mbar_expect(&mbf[s2_], 32768u); \
    const float* s_ = ((cc) < 4) ? (srcX + (cc) * 8192) : (srcH + ((cc) - 4) * 8192); \
    bulk_cp(stg + s2_ * 8192, s_, 32768u, &mbf[s2_]); } while (0)

#define ISSUE_B(cc) do { int s2_ = (cc) & 1; \
    mbar_expect(&mbf[s2_], 32768u); \
    bulk_cp(stg + s2_ * 8192, srcH0 + (cc) * 8192, 32768u, &mbf[s2_]); } while (0)

    float c0 = 0.f, c1 = 0.f, h0reg = 0.f, h1reg = 0.f, x1reg = 0.f;
    unsigned ph = 0;

    // ---- prologue: group B computes pw0(0) (gemm term zero) ----
    if (!isA) {
        size_t gp = (size_t)pj * 64 + pb;
        float gi = __ldg(&g_G0[gp]);
        float gg = __ldg(&g_G0[gp + 65536]);
        float go = __ldg(&g_G0[gp + 98304]);
        float cs = sigf(gi) * tanhf(gg);
        float hs = sigf(go) * tanhf(cs);
        c0 = cs; h0reg = hs;                       // t=0 always active
        __stcg(&g_H0R[0][ch_addr], tf32r(h0reg));
        float xv = __ldg(&seq[(size_t)pb * 1024 * 512 + pj]);
        x1reg = hs + xv;
        __stcg(&g_X1R[0][ch_addr], tf32r(x1reg));
        __stcg(&g_X1E[0][gcell], x1reg);
    }
    gbar(ph);

#pragma unroll 1
    for (int t = 0; t < 1024; t++) {
        const int p = t & 1;
        float ac0[4] = {0, 0, 0, 0}, ac1[4] = {0, 0, 0, 0};
        if (isA) {
            // ===== gemm1(t): [X1(t); H1(t-1)] @ [Wih1; Whh1]^T =====
            const float* srcX = g_X1R[p];
            const float* srcH = g_H1R[p ^ 1];
            if (tid == 0) { ISSUE_A(0); ISSUE_A(1); }
#pragma unroll 1
            for (int cc = 0; cc < 8; cc++) {
                int sl = cc & 1;
                mbar_wait(&mbf[sl], (cc >> 1) & 1);
                COMPX(cc * 16, sl);
                __syncwarp();
                if (lane == 0) mbar_arrive(&mbe[sl]);
                if (tid == 0 && cc < 6) {
                    mbar_wait(&mbe[sl], (cc >> 1) & 1);
                    ISSUE_A(cc + 2);
                }
            }
            RED_STORE();
            // ===== pw1(t) =====
            {
                float gi = GAT(0) + b1i, gf = GAT(1) + b1f;
                float gg = GAT(2) + b1g, go = GAT(3) + b1o;
                float cs = sigf(gf) * c1 + sigf(gi) * tanhf(gg);
                float hs = sigf(go) * tanhf(cs);
                float x1 = __ldcg(&g_X1E[p][gcell]);
                bool act = t < mylen;
                out[((size_t)pb * 1024 + t) * 512 + pj] = act ? (hs + x1) : 0.f;
                if (act) { c1 = cs; h1reg = hs; }
                __stcg(&g_H1R[p][ch_addr], tf32r(h1reg));
            }
        } else if (t < 1023) {
            // ===== gemm0(t+1): H0(t) @ Whh0^T, then pw0(t+1) =====
            const int t1 = t + 1;
            const float* srcH0 = g_H0R[p];
            size_t gp = ((size_t)t1 * 2048 + pj) * 64 + pb;
            float p0 = __ldg(&g_G0[gp]);
            float p1 = __ldg(&g_G0[gp + 32768]);
            float p2 = __ldg(&g_G0[gp + 65536]);
            float p3 = __ldg(&g_G0[gp + 98304]);
            float xvp = __ldg(&seq[((size_t)pb * 1024 + t1) * 512 + pj]);
            if (tid == 0) { ISSUE_B(0); ISSUE_B(1); }
#pragma unroll 1
            for (int cc = 0; cc < 4; cc++) {
                int sl = cc & 1;
                mbar_wait(&mbf[sl], (cc >> 1) & 1);
                COMPX(cc * 16, sl);
                __syncwarp();
                if (lane == 0) mbar_arrive(&mbe[sl]);
                if (tid == 0 && cc < 2) {
                    mbar_wait(&mbe[sl], 0);
                    ISSUE_B(cc + 2);
                }
            }
            RED_STORE();
            {
                float gi = p0 + GAT(0), gf = p1 + GAT(1);
                float gg = p2 + GAT(2), go = p3 + GAT(3);
                float cs = sigf(gf) * c0 + sigf(gi) * tanhf(gg);
                float hs = sigf(go) * tanhf(cs);
                if (t1 < mylen) { c0 = cs; h0reg = hs; }
                __stcg(&g_H0R[p ^ 1][ch_addr], tf32r(h0reg));
                x1reg = hs + xvp;
                __stcg(&g_X1R[p ^ 1][ch_addr], tf32r(x1reg));
                __stcg(&g_X1E[p ^ 1][gcell], x1reg);
            }
        }
        if (t < 1023) gbar(ph);
    }

    // ---- tail: final h, c ----
    {
        const size_t HO = (size_t)64 * 1024 * 512;
        if (isA) {
            out[HO + 32768 + gcell] = h1reg;
            out[HO + 98304 + gcell] = c1;
        } else {
            out[HO + gcell]         = h0reg;
            out[HO + 65536 + gcell] = c0;
        }
    }
}

extern "C" void kernel_launch(void* const* d_in, const int* in_sizes, int n_in,
                              void* d_out, int out_size) {
    const float* seq  = (const float*)d_in[0];
    const int*   slen = (const int*)d_in[1];
    const float* Wih  = (const float*)d_in[2];
    const float* Whh  = (const float*)d_in[3];
    const float* bih  = (const float*)d_in[4];
    const float* bhh  = (const float*)d_in[5];
    float* out = (float*)d_out;

    init_kernel<<<128, 256>>>();
    g0_kernel<<<dim3(32, 1024), GTHR>>>(seq, Wih, bih, bhh);
    wprep_kernel<<<NCTA, GTHR>>>(Wih, Whh);

    const int smem = (32768 + 16384 + 4224) * 4;   // 213504 B
    cudaFuncSetAttribute(lstm_kernel, cudaFuncAttributeMaxDynamicSharedMemorySize, smem);
    lstm_kernel<<<NCTA, NTHR, smem>>>(seq, slen, bih, bhh, out);
}

// round 17
// speedup vs baseline: 3.5705x; 1.0301x over previous
#include <cuda_runtime.h>
#include <cstdint>

#define NCTA 128
#define NTHR 256
#define GTHR 256
typedef unsigned long long ull;

// -------- device scratch --------
__device__ __align__(128) float g_G0[(size_t)1024 * 2048 * 64];  // [t][n][b] fp32 exact
__device__ __align__(128) float g_X1R[2][64 * 512];  // [b][kperm] tf32
__device__ __align__(128) float g_H1R[2][64 * 512];
__device__ __align__(128) float g_H0R[2][64 * 512];
__device__ __align__(128) float g_X1E[2][64 * 512];  // exact X1, [b][j]
__device__ __align__(128) float g_WPA[(size_t)64 * 32768];  // gemm1 W frags
__device__ __align__(128) float g_WPB[(size_t)64 * 16384];  // gemm0 W frags
__device__ unsigned g_bar;

#define FMA2(d, a, b) asm("fma.rn.f32x2 %0, %1, %2, %0;" : "+l"(d) : "l"(a), "l"(b))

#define MMA(d, a0, a1, a2, a3, b0, b1) \
    asm("mma.sync.aligned.m16n8k8.row.col.f32.tf32.tf32.f32 " \
        "{%0,%1,%2,%3}, {%4,%5,%6,%7}, {%8,%9}, {%0,%1,%2,%3};" \
        : "+f"(d[0]), "+f"(d[1]), "+f"(d[2]), "+f"(d[3]) \
        : "r"(a0), "r"(a1), "r"(a2), "r"(a3), "r"(b0), "r"(b1))

__device__ __forceinline__ float lohi(ull v) {
    return __uint_as_float((unsigned)v) + __uint_as_float((unsigned)(v >> 32));
}
__device__ __forceinline__ float sigf(float x) { return 1.f / (1.f + __expf(-x)); }
__device__ __forceinline__ float tf32r(float x) {
    unsigned u; asm("cvt.rna.tf32.f32 %0, %1;" : "=r"(u) : "f"(x));
    return __uint_as_float(u);
}

__device__ __forceinline__ void gbar(unsigned& ph) {
    __syncthreads();
    ph += NCTA;
    if (threadIdx.x == 0) {
        __threadfence();
        atomicAdd(&g_bar, 1u);
        while (*(volatile unsigned*)&g_bar < ph) { }
        __threadfence();
    }
    __syncthreads();
}

__global__ void init_kernel() {
    int i = blockIdx.x * blockDim.x + threadIdx.x;
    if (i == 0) g_bar = 0;
    if (i < 64 * 512) { g_H1R[0][i] = 0.f; g_H1R[1][i] = 0.f; }
}

// -------- weights -> per-(K8, nt) B-fragment layout, tf32-rounded --------
// float idx = (((K8*2 + ntp)*32 + lane)*4) + ntb*2 + breg, nt = ntp*2+ntb
// element: n32 = nt*8 + (lane>>2); orig k = K8*8 + (lane&3) + breg*4
__global__ __launch_bounds__(GTHR) void wprep_kernel(
    const float* __restrict__ Wih, const float* __restrict__ Whh)
{
    int bx = blockIdx.x;
    if (bx < 64) {
        for (int idx = threadIdx.x; idx < 32768; idx += GTHR) {
            int q = idx & 3, i4 = idx >> 2;
            int lane = i4 & 31, tmp = i4 >> 5;
            int ntp = tmp & 1, K8 = tmp >> 1;
            int nt = ntp * 2 + (q >> 1), breg = q & 1;
            int n32 = nt * 8 + (lane >> 2);
            int kk = K8 * 8 + (lane & 3) + breg * 4;
            int n1 = 2048 + (n32 >> 3) * 512 + bx * 8 + (n32 & 7);
            const float* src = (kk < 512) ? &Wih[(size_t)n1 * 512 + kk]
                                          : &Whh[(size_t)n1 * 512 + kk - 512];
            g_WPA[(size_t)bx * 32768 + idx] = tf32r(__ldg(src));
        }
    } else {
        int bxg = bx - 64;
        for (int idx = threadIdx.x; idx < 16384; idx += GTHR) {
            int q = idx & 3, i4 = idx >> 2;
            int lane = i4 & 31, tmp = i4 >> 5;
            int ntp = tmp & 1, K8 = tmp >> 1;
            int nt = ntp * 2 + (q >> 1), breg = q & 1;
            int n32 = nt * 8 + (lane >> 2);
            int kk = K8 * 8 + (lane & 3) + breg * 4;
            int n0 = (n32 >> 3) * 512 + bxg * 8 + (n32 & 7);
            g_WPB[(size_t)bxg * 16384 + idx] = tf32r(__ldg(&Whh[(size_t)n0 * 512 + kk]));
        }
    }
}

// -------- G0[t][n][b] = (seq @ W_ih0^T)(b,n) + biases  (exact fp32) --------
__global__ __launch_bounds__(GTHR) void g0_kernel(
    const float* __restrict__ seq, const float* __restrict__ Wih,
    const float* __restrict__ bih, const float* __restrict__ bhh)
{
    __shared__ float  xs[64 * 68];
    __shared__ float2 wst[32 * 66 + 64];
    const int t = blockIdx.y, nb = blockIdx.x;
    const int tid = threadIdx.x, tr = tid >> 4, tc = tid & 15;
    ull acc[4][4] = {};
    for (int kc = 0; kc < 8; kc++) {
        __syncthreads();
#pragma unroll
        for (int i = 0; i < 4; i++) {
            int s = i * 256 + tid, rr = s >> 4, c4 = s & 15;
            *(float4*)&xs[rr * 68 + c4 * 4] =
                *(const float4*)&seq[((size_t)rr * 1024 + t) * 512 + kc * 64 + c4 * 4];
            float4 wv = __ldg((const float4*)&Wih[((size_t)(nb * 64 + rr)) * 512 + kc * 64 + c4 * 4]);
            wst[(c4 * 2) * 66 + rr]     = make_float2(wv.x, wv.y);
            wst[(c4 * 2 + 1) * 66 + rr] = make_float2(wv.z, wv.w);
        }
        __syncthreads();
        const ull* wstu = (const ull*)wst;
#pragma unroll 4
        for (int k2 = 0; k2 < 32; k2++) {
            ull xr[4], wr[4];
#pragma unroll
            for (int i = 0; i < 4; i++) xr[i] = *(const ull*)&xs[(tr * 4 + i) * 68 + k2 * 2];
#pragma unroll
            for (int j = 0; j < 4; j++) wr[j] = wstu[k2 * 66 + j * 16 + tc];
#pragma unroll
            for (int i = 0; i < 4; i++)
#pragma unroll
                for (int j = 0; j < 4; j++) FMA2(acc[i][j], xr[i], wr[j]);
        }
    }
    float* smt = (float*)wst;
    __syncthreads();
#pragma unroll
    for (int i = 0; i < 4; i++)
#pragma unroll
        for (int j = 0; j < 4; j++)
            smt[(j * 16 + tc) * 68 + tr * 4 + i] = lohi(acc[i][j]);
    __syncthreads();
    for (int u = tid; u < 1024; u += GTHR) {
        int nloc = u >> 4, bq = u & 15;
        int n = nb * 64 + nloc;
        float bias = __ldg(&bih[n]) + __ldg(&bhh[n]);
        float4 v = *(const float4*)&smt[nloc * 68 + bq * 4];
        v.x += bias; v.y += bias; v.z += bias; v.w += bias;
        *(float4*)&g_G0[((size_t)t * 2048 + n) * 64 + bq * 4] = v;
    }
}

// -------- persistent recurrence: register weights, direct-L2 activations --------
__global__ __launch_bounds__(NTHR, 1) void lstm_kernel(
    const float* __restrict__ seq, const int* __restrict__ slen,
    const float* __restrict__ bih, const float* __restrict__ bhh,
    float* __restrict__ out)
{
    extern __shared__ float red[];        // [8 warps][33 n? -> n32*66 + row], 16896 floats

    const int tid = threadIdx.x, bx = blockIdx.x;
    const bool isA = bx < 64;
    const int bxg = isA ? bx : bx - 64;
    const int lane = tid & 31, wid = tid >> 5;
    const int r0 = lane >> 2, q = lane & 3;

    // pointwise: thread owns cells (pb, pj) and (pb, pj+4)
    const int pjl = tid >> 6, pb = tid & 63;
    const int pj = bxg * 8 + pjl;
    const int mylen = __ldg(&slen[pb]);
    float bA[2][4];
    if (isA) {
#pragma unroll
        for (int k = 0; k < 2; k++)
#pragma unroll
            for (int g = 0; g < 4; g++) {
                int n = 2048 + g * 512 + pj + 4 * k;
                bA[k][g] = __ldg(&bih[n]) + __ldg(&bhh[n]);
            }
    }

    // ---- weights into registers ----
    uint4 wr[16][2];
    if (isA) {
        const uint4* wp = (const uint4*)g_WPA + (size_t)bx * 8192;
#pragma unroll
        for (int k8 = 0; k8 < 16; k8++)
#pragma unroll
            for (int ntp = 0; ntp < 2; ntp++)
                wr[k8][ntp] = __ldg(&wp[((wid * 16 + k8) * 2 + ntp) * 32 + lane]);
    } else {
        const uint4* wp = (const uint4*)g_WPB + (size_t)bxg * 4096;
#pragma unroll
        for (int k8 = 0; k8 < 8; k8++)
#pragma unroll
            for (int ntp = 0; ntp < 2; ntp++)
                wr[k8][ntp] = __ldg(&wp[((wid * 8 + k8) * 2 + ntp) * 32 + lane]);
    }

    float cst[2] = {0.f, 0.f}, hst[2] = {0.f, 0.f};
    unsigned ph = 0;

    // ---- prologue: group B computes pw0(0) (gemm term zero) ----
    if (!isA) {
        float hr[2], xr[2];
#pragma unroll
        for (int k = 0; k < 2; k++) {
            int pjk = pj + 4 * k;
            size_t gp = (size_t)pjk * 64 + pb;
            float gi = __ldg(&g_G0[gp]);
            float gg = __ldg(&g_G0[gp + 65536]);
            float go = __ldg(&g_G0[gp + 98304]);
            float cs = sigf(gi) * tanhf(gg);
            float hs = sigf(go) * tanhf(cs);
            cst[k] = cs; hst[k] = hs;
            float x1 = hs + __ldg(&seq[(size_t)pb * 1024 * 512 + pjk]);
            __stcg(&g_X1E[0][pb * 512 + pjk], x1);
            hr[k] = tf32r(hs); xr[k] = tf32r(x1);
        }
        int sa = pb * 512 + bxg * 8 + 2 * pjl;
        __stcg((float2*)&g_H0R[0][sa], make_float2(hr[0], hr[1]));
        __stcg((float2*)&g_X1R[0][sa], make_float2(xr[0], xr[1]));
    }
    gbar(ph);

#pragma unroll 1
    for (int t = 0; t < 1024; t++) {
        const int p = t & 1;
        if (isA) {
            // ===== gemm1(t): [X1(t); H1(t-1)] @ W1^T =====
            const float* srcA = (wid < 4) ? g_X1R[p] : g_H1R[p ^ 1];
            const int kcol = (wid & 3) * 128 + q * 2;
            float x1a = __ldcg(&g_X1E[p][pb * 512 + pj]);
            float x1b = __ldcg(&g_X1E[p][pb * 512 + pj + 4]);
            uint2 ua[8], ub[8];
#pragma unroll
            for (int s = 0; s < 8; s++) {
                int ad = r0 * 512 + kcol + s * 8;
                ua[s] = __ldcg((const uint2*)&srcA[ad]);
                ub[s] = __ldcg((const uint2*)&srcA[ad + 4096]);
            }
#pragma unroll
            for (int mt = 0; mt < 4; mt++) {
                float ac[4][4] = {};
#pragma unroll
                for (int k8 = 0; k8 < 16; k8++) {
                    int i = mt * 16 + k8, s = i & 7;
                    uint2 a02 = ua[s], a13 = ub[s];
                    if (i < 56) {
                        int i2 = i + 8, mt2 = i2 >> 4, k82 = i2 & 15;
                        int ad = (mt2 * 16 + r0) * 512 + kcol + k82 * 8;
                        ua[s] = __ldcg((const uint2*)&srcA[ad]);
                        ub[s] = __ldcg((const uint2*)&srcA[ad + 4096]);
                    }
                    MMA(ac[0], a02.x, a13.x, a02.y, a13.y, wr[k8][0].x, wr[k8][0].y);
                    MMA(ac[1], a02.x, a13.x, a02.y, a13.y, wr[k8][0].z, wr[k8][0].w);
                    MMA(ac[2], a02.x, a13.x, a02.y, a13.y, wr[k8][1].x, wr[k8][1].y);
                    MMA(ac[3], a02.x, a13.x, a02.y, a13.y, wr[k8][1].z, wr[k8][1].w);
                }
#pragma unroll
                for (int nt = 0; nt < 4; nt++) {
                    float* rp = red + wid * 2112 + (nt * 8 + q * 2) * 66 + mt * 16 + r0;
                    rp[0] = ac[nt][0]; rp[66] = ac[nt][1];
                    rp[8] = ac[nt][2]; rp[74] = ac[nt][3];
                }
            }
            __syncthreads();
            // ===== pw1(t) =====
            float hr[2];
#pragma unroll
            for (int k = 0; k < 2; k++) {
                float g4[4];
#pragma unroll
                for (int g = 0; g < 4; g++) {
                    int n32 = g * 8 + pjl + 4 * k;
                    float s = 0.f;
#pragma unroll
                    for (int w = 0; w < 8; w++) s += red[w * 2112 + n32 * 66 + pb];
                    g4[g] = s + bA[k][g];
                }
                float cs = sigf(g4[1]) * cst[k] + sigf(g4[0]) * tanhf(g4[2]);
                float hs = sigf(g4[3]) * tanhf(cs);
                bool act = t < mylen;
                float x1 = k ? x1b : x1a;
                out[((size_t)pb * 1024 + t) * 512 + pj + 4 * k] = act ? (hs + x1) : 0.f;
                if (act) { cst[k] = cs; hst[k] = hs; }
                hr[k] = tf32r(hst[k]);
            }
            __stcg((float2*)&g_H1R[p][pb * 512 + bxg * 8 + 2 * pjl], make_float2(hr[0], hr[1]));
        } else if (t < 1023) {
            // ===== gemm0(t+1) + pw0(t+1) =====
            const int t1 = t + 1;
            float pg[2][4], xv[2];
#pragma unroll
            for (int k = 0; k < 2; k++) {
                size_t gp = ((size_t)t1 * 2048 + pj + 4 * k) * 64 + pb;
#pragma unroll
                for (int g = 0; g < 4; g++) pg[k][g] = __ldg(&g_G0[gp + (size_t)g * 32768]);
                xv[k] = __ldg(&seq[((size_t)pb * 1024 + t1) * 512 + pj + 4 * k]);
            }
            const float* srcA = g_H0R[p];
            const int kcol = wid * 64 + q * 2;
            uint2 ua[8], ub[8];
#pragma unroll
            for (int s = 0; s < 8; s++) {
                int ad = r0 * 512 + kcol + s * 8;
                ua[s] = __ldcg((const uint2*)&srcA[ad]);
                ub[s] = __ldcg((const uint2*)&srcA[ad + 4096]);
            }
#pragma unroll
            for (int mt = 0; mt < 4; mt++) {
                float ac[4][4] = {};
#pragma unroll
                for (int k8 = 0; k8 < 8; k8++) {
                    int i = mt * 8 + k8, s = i & 7;
                    uint2 a02 = ua[s], a13 = ub[s];
                    if (i < 24) {
                        int i2 = i + 8, mt2 = i2 >> 3, k82 = i2 & 7;
                        int ad = (mt2 * 16 + r0) * 512 + kcol + k82 * 8;
                        ua[s] = __ldcg((const uint2*)&srcA[ad]);
                        ub[s] = __ldcg((const uint2*)&srcA[ad + 4096]);
                    }
                    MMA(ac[0], a02.x, a13.x, a02.y, a13.y, wr[k8][0].x, wr[k8][0].y);
                    MMA(ac[1], a02.x, a13.x, a02.y, a13.y, wr[k8][0].z, wr[k8][0].w);
                    MMA(ac[2], a02.x, a13.x, a02.y, a13.y, wr[k8][1].x, wr[k8][1].y);
                    MMA(ac[3], a02.x, a13.x, a02.y, a13.y, wr[k8][1].z, wr[k8][1].w);
                }
#pragma unroll
                for (int nt = 0; nt < 4; nt++) {
                    float* rp = red + wid * 2112 + (nt * 8 + q * 2) * 66 + mt * 16 + r0;
                    rp[0] = ac[nt][0]; rp[66] = ac[nt][1];
                    rp[8] = ac[nt][2]; rp[74] = ac[nt][3];
                }
            }
            __syncthreads();
            float hr[2], xr[2];
#pragma unroll
            for (int k = 0; k < 2; k++) {
                float g4[4];
#pragma unroll
                for (int g = 0; g < 4; g++) {
                    int n32 = g * 8 + pjl + 4 * k;
                    float s = 0.f;
#pragma unroll
                    for (int w = 0; w < 8; w++) s += red[w * 2112 + n32 * 66 + pb];
                    g4[g] = s + pg[k][g];
                }
                float cs = sigf(g4[1]) * cst[k] + sigf(g4[0]) * tanhf(g4[2]);
                float hs = sigf(g4[3]) * tanhf(cs);
                if (t1 < mylen) { cst[k] = cs; hst[k] = hs; }
                float x1 = hst[k] * 0.f + hs + xv[k];   // x1 uses CURRENT hs (pre-freeze semantics match ref)
                x1 = hs + xv[k];
                __stcg(&g_X1E[p ^ 1][pb * 512 + pj + 4 * k], x1);
                hr[k] = tf32r(hst[k]); xr[k] = tf32r(x1);
            }
            int sa = pb * 512 + bxg * 8 + 2 * pjl;
            __stcg((float2*)&g_H0R[p ^ 1][sa], make_float2(hr[0], hr[1]));
            __stcg((float2*)&g_X1R[p ^ 1][sa], make_float2(xr[0], xr[1]));
        }
        if (t < 1023) gbar(ph);
    }

    // ---- tail: final h, c ----
    {
        const size_t HO = (size_t)64 * 1024 * 512;
        int gc0 = pb * 512 + pj, gc1 = gc0 + 4;
        if (isA) {
            out[HO + 32768 + gc0] = hst[0]; out[HO + 32768 + gc1] = hst[1];
            out[HO + 98304 + gc0] = cst[0]; out[HO + 98304 + gc1] = cst[1];
        } else {
            out[HO + gc0] = hst[0];         out[HO + gc1] = hst[1];
            out[HO + 65536 + gc0] = cst[0]; out[HO + 65536 + gc1] = cst[1];
        }
    }
}

extern "C" void kernel_launch(void* const* d_in, const int* in_sizes, int n_in,
                              void* d_out, int out_size) {
    const float* seq  = (const float*)d_in[0];
    const int*   slen = (const int*)d_in[1];
    const float* Wih  = (const float*)d_in[2];
    const float* Whh  = (const float*)d_in[3];
    const float* bih  = (const float*)d_in[4];
    const float* bhh  = (const float*)d_in[5];
    float* out = (float*)d_out;

    init_kernel<<<128, 256>>>();
    g0_kernel<<<dim3(32, 1024), GTHR>>>(seq, Wih, bih, bhh);
    wprep_kernel<<<NCTA, GTHR>>>(Wih, Whh);

    const int smem = 8 * 2112 * 4;   // 67584 B
    cudaFuncSetAttribute(lstm_kernel, cudaFuncAttributeMaxDynamicSharedMemorySize, smem);
    lstm_kernel<<<NCTA, NTHR, smem>>>(seq, slen, bih, bhh, out);
}